// round 7
// baseline (speedup 1.0000x reference)
#include <cuda_runtime.h>

typedef unsigned long long u64;

#define BT 4096      // B*T
#define DM 1024
#define NH 16
#define HD 64
#define TS 2048

// ---------------- scratch ----------------
__device__ float g_Q [BT*DM];   // 16 MB  (natural [bt][d])
__device__ float g_Kt[HD*BT];   // 1 MB   (TRANSPOSED: [kk][bt])
__device__ float g_V [BT*HD];   // 1 MB   (natural [bt][kk])
__device__ float g_Y [BT*DM];   // 16 MB

// ---------------- f32x2 packed helpers ----------------
__device__ __forceinline__ void fma2(u64& d, u64 a, u64 b){
    asm("fma.rn.f32x2 %0, %1, %2, %0;" : "+l"(d) : "l"(a), "l"(b));
}
__device__ __forceinline__ u64 dup2(float x){
    u64 r; asm("mov.b64 %0, {%1, %1};" : "=l"(r) : "f"(x)); return r;
}
__device__ __forceinline__ u64 mul2(u64 a, u64 b){
    u64 r; asm("mul.rn.f32x2 %0, %1, %2;" : "=l"(r) : "l"(a), "l"(b)); return r;
}
__device__ __forceinline__ float2 unpk(u64 v){
    float2 f; asm("mov.b64 {%0, %1}, %2;" : "=f"(f.x), "=f"(f.y) : "l"(v)); return f;
}

// ---------------- packed-fp32 GEMM: C[M,N] = A[M,K] @ B[K,N] ----------------
// 256 threads; (BM/TM)*(BN/TN) == 256. TRANS stores C transposed ([N][M]).
template<int BM, int BN, int BK, int TM, int TN, bool TRANS>
__global__ __launch_bounds__(256)
void sgemm2(const float* __restrict__ A, const float* __restrict__ Bm,
            float* __restrict__ C, int M, int N, int K)
{
    __shared__ float As[BK*BM];   // k-major (transposed A tile)
    __shared__ float Bs[BK*BN];

    const int tid = threadIdx.x;
    const int tc  = tid % (BN/TN);
    const int tr  = tid / (BN/TN);
    const int rowBase = blockIdx.y * BM;
    const int colBase = blockIdx.x * BN;

    const int irA = tid / (BK/4);
    const int icA = (tid % (BK/4)) * 4;
    constexpr int sA = (256*4)/BK;
    const int irB = tid / (BN/4);
    const int icB = (tid % (BN/4)) * 4;
    constexpr int sB = (256*4)/BN;

    u64 res2[TM*(TN/2)];
    #pragma unroll
    for (int i = 0; i < TM*(TN/2); ++i) res2[i] = 0ull;

    for (int bk = 0; bk < K; bk += BK) {
        #pragma unroll
        for (int off = 0; off < BM; off += sA) {
            float4 t = *(const float4*)&A[(rowBase+irA+off)*K + bk + icA];
            As[(icA+0)*BM + irA+off] = t.x;
            As[(icA+1)*BM + irA+off] = t.y;
            As[(icA+2)*BM + irA+off] = t.z;
            As[(icA+3)*BM + irA+off] = t.w;
        }
        #pragma unroll
        for (int off = 0; off < BK; off += sB)
            *(float4*)&Bs[(irB+off)*BN + icB] =
                *(const float4*)&Bm[(bk+irB+off)*N + colBase + icB];
        __syncthreads();

        #pragma unroll
        for (int kk = 0; kk < BK; ++kk) {
            float regM[TM];
            u64 regN[TN/2];
            #pragma unroll
            for (int q = 0; q < TM/4; ++q)
                *(float4*)&regM[q*4] = *(const float4*)&As[kk*BM + tr*TM + q*4];
            #pragma unroll
            for (int q = 0; q < TN/4; ++q) {
                ulonglong2 t = *(const ulonglong2*)&Bs[kk*BN + tc*TN + q*4];
                regN[q*2] = t.x; regN[q*2+1] = t.y;
            }
            #pragma unroll
            for (int i = 0; i < TM; ++i) {
                u64 a = dup2(regM[i]);
                #pragma unroll
                for (int j = 0; j < TN/2; ++j)
                    fma2(res2[i*(TN/2)+j], a, regN[j]);
            }
        }
        __syncthreads();
    }

    if (!TRANS) {
        #pragma unroll
        for (int i = 0; i < TM; ++i)
            #pragma unroll
            for (int jq = 0; jq < TN/4; ++jq) {
                float2 a = unpk(res2[i*(TN/2)+jq*2]);
                float2 b = unpk(res2[i*(TN/2)+jq*2+1]);
                float4 o = make_float4(a.x, a.y, b.x, b.y);
                *(float4*)&C[(rowBase+tr*TM+i)*N + colBase+tc*TN+jq*4] = o;
            }
    } else {
        float rs[TM*TN];
        #pragma unroll
        for (int i = 0; i < TM; ++i)
            #pragma unroll
            for (int j = 0; j < TN/2; ++j) {
                float2 a = unpk(res2[i*(TN/2)+j]);
                rs[i*TN + j*2]   = a.x;
                rs[i*TN + j*2+1] = a.y;
            }
        #pragma unroll
        for (int j = 0; j < TN; ++j)
            #pragma unroll
            for (int iq = 0; iq < TM/4; ++iq) {
                float4 o = make_float4(rs[(iq*4+0)*TN+j], rs[(iq*4+1)*TN+j],
                                       rs[(iq*4+2)*TN+j], rs[(iq*4+3)*TN+j]);
                *(float4*)&C[(colBase+tc*TN+j)*M + rowBase+tr*TM+iq*4] = o;
            }
    }
}

// ---------------- causal MQA flash attention (f32x2, 4x8 per-thread tile) ---
// Grid: (32 q-tiles, 16 heads, 2 batches). 128 threads = 16(ty) x 8(tx).
// Thread owns S rows ty*4..+3, cols tx*8..+7 (16 f32x2) and O rows ty*4..+3,
// dims tx*8..+7 (16 f32x2). Row softmax reductions live in 8-lane shfl groups.
__global__ __launch_bounds__(128, 4)
void flash3(const float* __restrict__ Q, const float* __restrict__ Kt,
            const float* __restrict__ V, float* __restrict__ Y)
{
    extern __shared__ float smx[];
    float* Qt  = smx;             // [64][68]  kk-major Q (pre-scaled)
    float* KtP = smx + 64*68;     // [64][68]  kk-major K; reused as P [r][c]
    float* Vs  = smx + 2*64*68;   // [64][68]  c-major V

    const int qt = blockIdx.x, h = blockIdx.y, b = blockIdx.z;
    const int tid = threadIdx.x;
    const int ty = tid >> 3, tx = tid & 7;
    const int rowQ0 = b*TS + qt*64;
    const int rowK0 = b*TS;

    // Load Q tile, transpose to kk-major, pre-scale by 1/sqrt(64).
    #pragma unroll
    for (int p = 0; p < 8; ++p) {
        int lin = p*512 + tid*4;
        int r = lin >> 6, d = lin & 63;
        float4 q = *(const float4*)&Q[(rowQ0+r)*DM + h*HD + d];
        Qt[(d+0)*68 + r] = q.x * 0.125f;
        Qt[(d+1)*68 + r] = q.y * 0.125f;
        Qt[(d+2)*68 + r] = q.z * 0.125f;
        Qt[(d+3)*68 + r] = q.w * 0.125f;
    }

    u64 acc2[16];
    #pragma unroll
    for (int i = 0; i < 16; ++i) acc2[i] = 0ull;
    float mprev[4], lsum[4];
    #pragma unroll
    for (int i = 0; i < 4; ++i) { mprev[i] = -1e30f; lsum[i] = 0.f; }

    for (int kt = 0; kt <= qt; ++kt) {
        __syncthreads();   // prev iter done with KtP/Vs (and Qt visible, iter 0)
        #pragma unroll
        for (int p = 0; p < 8; ++p) {
            int lin = p*512 + tid*4;
            int a = lin >> 6, e = lin & 63;
            *(float4*)&KtP[a*68 + e] = *(const float4*)&Kt[a*BT + rowK0 + kt*64 + e];
            *(float4*)&Vs [a*68 + e] = *(const float4*)&V[(rowK0 + kt*64 + a)*HD + e];
        }
        __syncthreads();

        // S = Q @ K^T : per kk, 3 LDS.128 + 4 dup + 16 fma2
        u64 s2[16];
        #pragma unroll
        for (int i = 0; i < 16; ++i) s2[i] = 0ull;
        #pragma unroll 8
        for (int kk = 0; kk < 64; ++kk) {
            float4 q4 = *(const float4*)&Qt[kk*68 + ty*4];
            ulonglong2 ka = *(const ulonglong2*)&KtP[kk*68 + tx*8];
            ulonglong2 kb = *(const ulonglong2*)&KtP[kk*68 + tx*8 + 4];
            u64 a0 = dup2(q4.x), a1 = dup2(q4.y), a2 = dup2(q4.z), a3 = dup2(q4.w);
            fma2(s2[ 0],a0,ka.x); fma2(s2[ 1],a0,ka.y); fma2(s2[ 2],a0,kb.x); fma2(s2[ 3],a0,kb.y);
            fma2(s2[ 4],a1,ka.x); fma2(s2[ 5],a1,ka.y); fma2(s2[ 6],a1,kb.x); fma2(s2[ 7],a1,kb.y);
            fma2(s2[ 8],a2,ka.x); fma2(s2[ 9],a2,ka.y); fma2(s2[10],a2,kb.x); fma2(s2[11],a2,kb.y);
            fma2(s2[12],a3,ka.x); fma2(s2[13],a3,ka.y); fma2(s2[14],a3,kb.x); fma2(s2[15],a3,kb.y);
        }

        float s[32];
        #pragma unroll
        for (int i = 0; i < 4; ++i)
            #pragma unroll
            for (int p = 0; p < 4; ++p) {
                float2 a = unpk(s2[i*4+p]);
                s[i*8 + p*2]     = a.x;
                s[i*8 + p*2 + 1] = a.y;
            }

        if (kt == qt) {   // causal mask, diagonal tile only
            #pragma unroll
            for (int i = 0; i < 4; ++i)
                #pragma unroll
                for (int j = 0; j < 8; ++j)
                    if (tx*8+j > ty*4+i) s[i*8+j] = -1e30f;
        }

        // Online softmax: rows spread over 8 tx lanes (3-step shfl)
        #pragma unroll
        for (int i = 0; i < 4; ++i) {
            float mx = s[i*8];
            #pragma unroll
            for (int j = 1; j < 8; ++j) mx = fmaxf(mx, s[i*8+j]);
            #pragma unroll
            for (int o = 4; o; o >>= 1) mx = fmaxf(mx, __shfl_xor_sync(0xffffffffu, mx, o));
            float mnew = fmaxf(mprev[i], mx);
            float sc   = __expf(mprev[i] - mnew);
            float rs = 0.f;
            #pragma unroll
            for (int j = 0; j < 8; ++j) { s[i*8+j] = __expf(s[i*8+j] - mnew); rs += s[i*8+j]; }
            #pragma unroll
            for (int o = 4; o; o >>= 1) rs += __shfl_xor_sync(0xffffffffu, rs, o);
            lsum[i]  = lsum[i]*sc + rs;
            mprev[i] = mnew;
            u64 sc2 = dup2(sc);
            #pragma unroll
            for (int p = 0; p < 4; ++p) acc2[i*4+p] = mul2(acc2[i*4+p], sc2);
        }

        // Stage P row-major into the K buffer
        __syncthreads();
        #pragma unroll
        for (int i = 0; i < 4; ++i) {
            *(float4*)&KtP[(ty*4+i)*68 + tx*8]     = *(float4*)&s[i*8];
            *(float4*)&KtP[(ty*4+i)*68 + tx*8 + 4] = *(float4*)&s[i*8+4];
        }
        __syncthreads();

        // O += P @ V : per cq (4 keys), 12 LDS.128 + 16 dup + 64 fma2
        #pragma unroll 2
        for (int cq = 0; cq < 16; ++cq) {
            float rp[16];
            #pragma unroll
            for (int i = 0; i < 4; ++i)
                *(float4*)&rp[i*4] = *(const float4*)&KtP[(ty*4+i)*68 + cq*4];
            #pragma unroll
            for (int q = 0; q < 4; ++q) {
                int c = cq*4 + q;
                ulonglong2 va = *(const ulonglong2*)&Vs[c*68 + tx*8];
                ulonglong2 vb = *(const ulonglong2*)&Vs[c*68 + tx*8 + 4];
                #pragma unroll
                for (int i = 0; i < 4; ++i) {
                    u64 a = dup2(rp[i*4+q]);
                    fma2(acc2[i*4+0], a, va.x);
                    fma2(acc2[i*4+1], a, va.y);
                    fma2(acc2[i*4+2], a, vb.x);
                    fma2(acc2[i*4+3], a, vb.y);
                }
            }
        }
    }

    // Normalize + write Y (natural layout for the output projection)
    #pragma unroll
    for (int i = 0; i < 4; ++i) {
        float inv = 1.f / lsum[i];
        float2 a = unpk(acc2[i*4]),   bq = unpk(acc2[i*4+1]);
        float2 c = unpk(acc2[i*4+2]), dq = unpk(acc2[i*4+3]);
        float4 o1 = make_float4(a.x*inv, a.y*inv, bq.x*inv, bq.y*inv);
        float4 o2 = make_float4(c.x*inv, c.y*inv, dq.x*inv, dq.y*inv);
        *(float4*)&Y[(rowQ0+ty*4+i)*DM + h*HD + tx*8]     = o1;
        *(float4*)&Y[(rowQ0+ty*4+i)*DM + h*HD + tx*8 + 4] = o2;
    }
}

// ---------------- launch ----------------
extern "C" void kernel_launch(void* const* d_in, const int* in_sizes, int n_in,
                              void* d_out, int out_size) {
    const float* x  = (const float*)d_in[0];
    const float* Wq = (const float*)d_in[1];
    const float* Wk = (const float*)d_in[2];
    const float* Wv = (const float*)d_in[3];
    const float* Wo = (const float*)d_in[4];
    float* out = (float*)d_out;

    float *Qb, *Ktb, *Vb, *Yb;
    cudaGetSymbolAddress((void**)&Qb,  g_Q);
    cudaGetSymbolAddress((void**)&Ktb, g_Kt);
    cudaGetSymbolAddress((void**)&Vb,  g_V);
    cudaGetSymbolAddress((void**)&Yb,  g_Y);

    const int fsm = 3 * 64 * 68 * (int)sizeof(float);  // 52224 B
    cudaFuncSetAttribute(flash3, cudaFuncAttributeMaxDynamicSharedMemorySize, fsm);

    // Q = x @ Wq                          (4096 x 1024 x 1024)
    sgemm2<128,128,16,8,8,false><<<dim3(DM/128, BT/128), 256>>>(x, Wq, Qb, BT, DM, DM);
    // K^T = (x @ Wk)^T  -> [64][4096]     (transposed store)
    sgemm2<64,64,16,4,4,true>   <<<dim3(1, BT/64), 256>>>(x, Wk, Ktb, BT, HD, DM);
    // V = x @ Wv                          (natural [4096][64])
    sgemm2<64,64,16,4,4,false>  <<<dim3(1, BT/64), 256>>>(x, Wv, Vb, BT, HD, DM);
    // causal MQA attention -> Y
    flash3<<<dim3(TS/64, NH, 2), 128, fsm>>>(Qb, Ktb, Vb, Yb);
    // out = Y @ Wo                        (4096 x 1024 x 1024)
    sgemm2<128,128,16,8,8,false><<<dim3(DM/128, BT/128), 256>>>(Yb, Wo, out, BT, DM, DM);
}

// round 9
// speedup vs baseline: 1.2515x; 1.2515x over previous
#include <cuda_runtime.h>
#include <mma.h>
#include <cstdint>

using namespace nvcuda;
typedef unsigned long long u64;

#define BT 4096      // B*T
#define DM 1024
#define NH 16
#define HD 64
#define TS 2048

// ---------------- scratch ----------------
__device__ float g_Q [BT*DM];   // 16 MB (natural [bt][d])
__device__ float g_Kt[HD*BT];   // 1 MB  (TRANSPOSED: [kk][bt])
__device__ float g_V [BT*HD];   // 1 MB  (natural [bt][kk])
__device__ float g_Y [BT*DM];   // 16 MB

// ---------------- f32x2 packed helpers ----------------
__device__ __forceinline__ void fma2(u64& d, u64 a, u64 b){
    asm("fma.rn.f32x2 %0, %1, %2, %0;" : "+l"(d) : "l"(a), "l"(b));
}
__device__ __forceinline__ u64 dup2(float x){
    u64 r; asm("mov.b64 %0, {%1, %1};" : "=l"(r) : "f"(x)); return r;
}
__device__ __forceinline__ u64 mul2(u64 a, u64 b){
    u64 r; asm("mul.rn.f32x2 %0, %1, %2;" : "=l"(r) : "l"(a), "l"(b)); return r;
}
__device__ __forceinline__ float2 unpk(u64 v){
    float2 f; asm("mov.b64 {%0, %1}, %2;" : "=f"(f.x), "=f"(f.y) : "l"(v)); return f;
}
__device__ __forceinline__ void cpasync16(uint32_t dst, const float* src){
    asm volatile("cp.async.cg.shared.global [%0], [%1], 16;" :: "r"(dst), "l"(src) : "memory");
}
__device__ __forceinline__ uint32_t smem_u32(const void* p){
    uint32_t a; asm("{ .reg .u64 t; cvta.to.shared.u64 t, %1; cvt.u32.u64 %0, t; }"
                    : "=r"(a) : "l"(p)); return a;
}

// ---------------- wmma tf32 GEMM: C[M,N] = A[M,K] @ B[K,N] ------------------
// Block tile 128x128, BK=32, 8 warps (2 along M x 4 along N), warp tile 64x32
// = 4x2 wmma m16n16k8 fragments. 2-stage cp.async pipeline. fp32 accumulate.
#define WLDA 36    // A tile leading dim (floats), 128 rows
#define WLDB 132   // B tile leading dim (floats), 32 rows
#define WSTAGE (128*WLDA + 32*WLDB)   // floats per stage = 8832

__global__ __launch_bounds__(256)
void wgemm(const float* __restrict__ A, const float* __restrict__ B,
           float* __restrict__ C, int M, int N, int K)
{
    extern __shared__ float ws[];
    float* As[2] = { ws,                ws + WSTAGE };
    float* Bs[2] = { ws + 128*WLDA,     ws + WSTAGE + 128*WLDA };
    const uint32_t sbase = smem_u32(ws);

    const int tid = threadIdx.x;
    const int wid = tid >> 5;
    const int wm  = wid & 1;        // 0..1 : 64-row strip
    const int wn  = wid >> 1;       // 0..3 : 32-col strip
    const int rowBase = blockIdx.y * 128;
    const int colBase = blockIdx.x * 128;

    auto load_stage = [&](int it, int s){
        const int bk = it * 32;
        const uint32_t sa = sbase + (uint32_t)s * (WSTAGE*4u);
        // A tile: 128 rows x 32 floats  -> 1024 16B chunks
        #pragma unroll
        for (int i = 0; i < 4; ++i) {
            int c = tid + 256*i;
            int row = c >> 3, seg = c & 7;
            cpasync16(sa + (uint32_t)(row*WLDA + seg*4)*4u,
                      &A[(u64)(rowBase+row)*K + bk + seg*4]);
        }
        // B tile: 32 rows x 128 floats -> 1024 16B chunks
        const uint32_t sbB = sa + 128u*WLDA*4u;
        #pragma unroll
        for (int i = 0; i < 4; ++i) {
            int c = tid + 256*i;
            int row = c >> 5, seg = c & 31;
            cpasync16(sbB + (uint32_t)(row*WLDB + seg*4)*4u,
                      &B[(u64)(bk+row)*N + colBase + seg*4]);
        }
        asm volatile("cp.async.commit_group;" ::: "memory");
    };

    wmma::fragment<wmma::accumulator, 16, 16, 8, float> acc[4][2];
    #pragma unroll
    for (int i = 0; i < 4; ++i)
        #pragma unroll
        for (int j = 0; j < 2; ++j)
            wmma::fill_fragment(acc[i][j], 0.0f);

    const int nIt = K / 32;
    load_stage(0, 0);
    load_stage(1, 1);

    for (int it = 0; it < nIt; ++it) {
        const int s = it & 1;
        if (it + 2 < nIt) asm volatile("cp.async.wait_group 1;" ::: "memory");
        else              asm volatile("cp.async.wait_group 0;" ::: "memory");
        __syncthreads();

        #pragma unroll
        for (int ks = 0; ks < 32; ks += 8) {
            wmma::fragment<wmma::matrix_a, 16, 16, 8, wmma::precision::tf32, wmma::row_major> af[4];
            wmma::fragment<wmma::matrix_b, 16, 16, 8, wmma::precision::tf32, wmma::row_major> bf[2];
            #pragma unroll
            for (int i = 0; i < 4; ++i) {
                wmma::load_matrix_sync(af[i], &As[s][(wm*64 + i*16)*WLDA + ks], WLDA);
                #pragma unroll
                for (int t = 0; t < af[i].num_elements; ++t)
                    af[i].x[t] = wmma::__float_to_tf32(af[i].x[t]);
            }
            #pragma unroll
            for (int j = 0; j < 2; ++j) {
                wmma::load_matrix_sync(bf[j], &Bs[s][ks*WLDB + wn*32 + j*16], WLDB);
                #pragma unroll
                for (int t = 0; t < bf[j].num_elements; ++t)
                    bf[j].x[t] = wmma::__float_to_tf32(bf[j].x[t]);
            }
            #pragma unroll
            for (int i = 0; i < 4; ++i)
                #pragma unroll
                for (int j = 0; j < 2; ++j)
                    wmma::mma_sync(acc[i][j], af[i], bf[j], acc[i][j]);
        }
        __syncthreads();
        if (it + 2 < nIt) load_stage(it + 2, s);
    }

    #pragma unroll
    for (int i = 0; i < 4; ++i)
        #pragma unroll
        for (int j = 0; j < 2; ++j)
            wmma::store_matrix_sync(
                &C[(u64)(rowBase + wm*64 + i*16)*N + colBase + wn*32 + j*16],
                acc[i][j], N, wmma::mem_row_major);
}

// ---------------- scalar packed GEMM for small K/V projections --------------
template<int BM, int BN, int BK, int TM, int TN, bool TRANS>
__global__ __launch_bounds__(256)
void sgemm2(const float* __restrict__ A, const float* __restrict__ Bm,
            float* __restrict__ C, int M, int N, int K)
{
    __shared__ float As[BK*BM];
    __shared__ float Bs[BK*BN];

    const int tid = threadIdx.x;
    const int tc  = tid % (BN/TN);
    const int tr  = tid / (BN/TN);
    const int rowBase = blockIdx.y * BM;
    const int colBase = blockIdx.x * BN;

    const int irA = tid / (BK/4);
    const int icA = (tid % (BK/4)) * 4;
    constexpr int sA = (256*4)/BK;
    const int irB = tid / (BN/4);
    const int icB = (tid % (BN/4)) * 4;
    constexpr int sB = (256*4)/BN;

    u64 res2[TM*(TN/2)];
    #pragma unroll
    for (int i = 0; i < TM*(TN/2); ++i) res2[i] = 0ull;

    for (int bk = 0; bk < K; bk += BK) {
        #pragma unroll
        for (int off = 0; off < BM; off += sA) {
            float4 t = *(const float4*)&A[(rowBase+irA+off)*K + bk + icA];
            As[(icA+0)*BM + irA+off] = t.x;
            As[(icA+1)*BM + irA+off] = t.y;
            As[(icA+2)*BM + irA+off] = t.z;
            As[(icA+3)*BM + irA+off] = t.w;
        }
        #pragma unroll
        for (int off = 0; off < BK; off += sB)
            *(float4*)&Bs[(irB+off)*BN + icB] =
                *(const float4*)&Bm[(bk+irB+off)*N + colBase + icB];
        __syncthreads();

        #pragma unroll
        for (int kk = 0; kk < BK; ++kk) {
            float regM[TM]; u64 regN[TN/2];
            #pragma unroll
            for (int q = 0; q < TM/4; ++q)
                *(float4*)&regM[q*4] = *(const float4*)&As[kk*BM + tr*TM + q*4];
            #pragma unroll
            for (int q = 0; q < TN/4; ++q) {
                ulonglong2 t = *(const ulonglong2*)&Bs[kk*BN + tc*TN + q*4];
                regN[q*2] = t.x; regN[q*2+1] = t.y;
            }
            #pragma unroll
            for (int i = 0; i < TM; ++i) {
                u64 a = dup2(regM[i]);
                #pragma unroll
                for (int j = 0; j < TN/2; ++j) fma2(res2[i*(TN/2)+j], a, regN[j]);
            }
        }
        __syncthreads();
    }

    if (!TRANS) {
        #pragma unroll
        for (int i = 0; i < TM; ++i)
            #pragma unroll
            for (int jq = 0; jq < TN/4; ++jq) {
                float2 a = unpk(res2[i*(TN/2)+jq*2]);
                float2 b = unpk(res2[i*(TN/2)+jq*2+1]);
                *(float4*)&C[(rowBase+tr*TM+i)*N + colBase+tc*TN+jq*4] =
                    make_float4(a.x, a.y, b.x, b.y);
            }
    } else {
        float rs[TM*TN];
        #pragma unroll
        for (int i = 0; i < TM; ++i)
            #pragma unroll
            for (int j = 0; j < TN/2; ++j) {
                float2 a = unpk(res2[i*(TN/2)+j]);
                rs[i*TN + j*2] = a.x; rs[i*TN + j*2+1] = a.y;
            }
        #pragma unroll
        for (int j = 0; j < TN; ++j)
            #pragma unroll
            for (int iq = 0; iq < TM/4; ++iq)
                *(float4*)&C[(colBase+tc*TN+j)*M + rowBase+tr*TM+iq*4] =
                    make_float4(rs[(iq*4+0)*TN+j], rs[(iq*4+1)*TN+j],
                                rs[(iq*4+2)*TN+j], rs[(iq*4+3)*TN+j]);
    }
}

// ---------------- causal MQA flash attention (flash2, known-good) -----------
__global__ __launch_bounds__(256)
void flash2(const float* __restrict__ Q, const float* __restrict__ Kt,
            const float* __restrict__ V, float* __restrict__ Y)
{
    extern __shared__ float smx[];
    float* Qt  = smx;             // [64][68]  kk-major Q (pre-scaled)
    float* KtP = smx + 64*68;     // [64][68]  kk-major K; reused as P^T
    float* Vs  = smx + 2*64*68;   // [64][68]  c-major V

    const int qt = blockIdx.x, h = blockIdx.y, b = blockIdx.z;
    const int tid = threadIdx.x;
    const int ty = tid >> 4, tx = tid & 15;
    const int rowQ0 = b*TS + qt*64;
    const int rowK0 = b*TS;

    #pragma unroll
    for (int p = 0; p < 4; ++p) {
        int lin = p*1024 + tid*4;
        int r = lin >> 6, d = lin & 63;
        float4 q = *(const float4*)&Q[(rowQ0+r)*DM + h*HD + d];
        Qt[(d+0)*68 + r] = q.x * 0.125f;
        Qt[(d+1)*68 + r] = q.y * 0.125f;
        Qt[(d+2)*68 + r] = q.z * 0.125f;
        Qt[(d+3)*68 + r] = q.w * 0.125f;
    }

    u64 acc2[8];
    #pragma unroll
    for (int i = 0; i < 8; ++i) acc2[i] = 0ull;
    float mprev[4], lsum[4];
    #pragma unroll
    for (int i = 0; i < 4; ++i) { mprev[i] = -1e30f; lsum[i] = 0.f; }

    for (int kt = 0; kt <= qt; ++kt) {
        __syncthreads();
        #pragma unroll
        for (int p = 0; p < 4; ++p) {
            int lin = p*1024 + tid*4;
            int a = lin >> 6, e = lin & 63;
            *(float4*)&KtP[a*68 + e] = *(const float4*)&Kt[a*BT + rowK0 + kt*64 + e];
            *(float4*)&Vs [a*68 + e] = *(const float4*)&V[(rowK0 + kt*64 + a)*HD + e];
        }
        __syncthreads();

        u64 s2[8];
        #pragma unroll
        for (int i = 0; i < 8; ++i) s2[i] = 0ull;
        #pragma unroll 16
        for (int kk = 0; kk < 64; ++kk) {
            float4 q4 = *(const float4*)&Qt[kk*68 + ty*4];
            ulonglong2 k2 = *(const ulonglong2*)&KtP[kk*68 + tx*4];
            u64 a0 = dup2(q4.x), a1 = dup2(q4.y), a2 = dup2(q4.z), a3 = dup2(q4.w);
            fma2(s2[0],a0,k2.x); fma2(s2[1],a0,k2.y);
            fma2(s2[2],a1,k2.x); fma2(s2[3],a1,k2.y);
            fma2(s2[4],a2,k2.x); fma2(s2[5],a2,k2.y);
            fma2(s2[6],a3,k2.x); fma2(s2[7],a3,k2.y);
        }

        float s[16];
        #pragma unroll
        for (int i = 0; i < 4; ++i) {
            float2 a = unpk(s2[i*2]), c = unpk(s2[i*2+1]);
            s[i*4+0]=a.x; s[i*4+1]=a.y; s[i*4+2]=c.x; s[i*4+3]=c.y;
        }

        if (kt == qt) {
            #pragma unroll
            for (int i = 0; i < 4; ++i)
                #pragma unroll
                for (int j = 0; j < 4; ++j)
                    if (tx*4+j > ty*4+i) s[i*4+j] = -1e30f;
        }

        #pragma unroll
        for (int i = 0; i < 4; ++i) {
            float mx = fmaxf(fmaxf(s[i*4],s[i*4+1]), fmaxf(s[i*4+2],s[i*4+3]));
            #pragma unroll
            for (int o = 8; o; o >>= 1) mx = fmaxf(mx, __shfl_xor_sync(0xffffffffu, mx, o));
            float mnew = fmaxf(mprev[i], mx);
            float sc   = __expf(mprev[i] - mnew);
            float rs = 0.f;
            #pragma unroll
            for (int j = 0; j < 4; ++j) { s[i*4+j] = __expf(s[i*4+j] - mnew); rs += s[i*4+j]; }
            #pragma unroll
            for (int o = 8; o; o >>= 1) rs += __shfl_xor_sync(0xffffffffu, rs, o);
            lsum[i]  = lsum[i]*sc + rs;
            mprev[i] = mnew;
            u64 sc2 = dup2(sc);
            acc2[i*2]   = mul2(acc2[i*2],   sc2);
            acc2[i*2+1] = mul2(acc2[i*2+1], sc2);
        }

        __syncthreads();
        #pragma unroll
        for (int j = 0; j < 4; ++j)
            #pragma unroll
            for (int i = 0; i < 4; ++i)
                KtP[(tx*4+j)*68 + ty*4+i] = s[i*4+j];
        __syncthreads();

        #pragma unroll 4
        for (int c = 0; c < 64; ++c) {
            float rp[4];
            #pragma unroll
            for (int i = 0; i < 4; ++i) rp[i] = KtP[c*68 + ty*4+i];
            ulonglong2 v2 = *(const ulonglong2*)&Vs[c*68 + tx*4];
            #pragma unroll
            for (int i = 0; i < 4; ++i) {
                u64 a = dup2(rp[i]);
                fma2(acc2[i*2],   a, v2.x);
                fma2(acc2[i*2+1], a, v2.y);
            }
        }
    }

    #pragma unroll
    for (int i = 0; i < 4; ++i) {
        float inv = 1.f / lsum[i];
        float2 a = unpk(acc2[i*2]), c = unpk(acc2[i*2+1]);
        *(float4*)&Y[(rowQ0+ty*4+i)*DM + h*HD + tx*4] =
            make_float4(a.x*inv, a.y*inv, c.x*inv, c.y*inv);
    }
}

// ---------------- launch ----------------
extern "C" void kernel_launch(void* const* d_in, const int* in_sizes, int n_in,
                              void* d_out, int out_size) {
    const float* x  = (const float*)d_in[0];
    const float* Wq = (const float*)d_in[1];
    const float* Wk = (const float*)d_in[2];
    const float* Wv = (const float*)d_in[3];
    const float* Wo = (const float*)d_in[4];
    float* out = (float*)d_out;

    float *Qb, *Ktb, *Vb, *Yb;
    cudaGetSymbolAddress((void**)&Qb,  g_Q);
    cudaGetSymbolAddress((void**)&Ktb, g_Kt);
    cudaGetSymbolAddress((void**)&Vb,  g_V);
    cudaGetSymbolAddress((void**)&Yb,  g_Y);

    const int fsm = 3 * 64 * 68 * (int)sizeof(float);   // 52224 B
    cudaFuncSetAttribute(flash2, cudaFuncAttributeMaxDynamicSharedMemorySize, fsm);
    const int gsm = 2 * WSTAGE * (int)sizeof(float);    // 70656 B
    cudaFuncSetAttribute(wgemm, cudaFuncAttributeMaxDynamicSharedMemorySize, gsm);

    // Q = x @ Wq  (wmma tf32)
    wgemm<<<dim3(DM/128, BT/128), 256, gsm>>>(x, Wq, Qb, BT, DM, DM);
    // K^T = (x @ Wk)^T  -> [64][4096]
    sgemm2<64,64,16,4,4,true> <<<dim3(1, BT/64), 256>>>(x, Wk, Ktb, BT, HD, DM);
    // V = x @ Wv
    sgemm2<64,64,16,4,4,false><<<dim3(1, BT/64), 256>>>(x, Wv, Vb, BT, HD, DM);
    // causal MQA attention -> Y
    flash2<<<dim3(TS/64, NH, 2), 256, fsm>>>(Qb, Ktb, Vb, Yb);
    // out = Y @ Wo  (wmma tf32)
    wgemm<<<dim3(DM/128, BT/128), 256, gsm>>>(Yb, Wo, out, BT, DM, DM);
}

// round 10
// speedup vs baseline: 1.3071x; 1.0444x over previous
#include <cuda_runtime.h>
#include <mma.h>
#include <cstdint>

using namespace nvcuda;
typedef unsigned long long u64;

#define BT 4096      // B*T
#define DM 1024
#define NH 16
#define HD 64
#define TS 2048

// ---------------- scratch ----------------
__device__ float g_Q  [BT*DM];   // 16 MB (natural [bt][d])
__device__ float g_Kt [HD*BT];   // 1 MB  (TRANSPOSED: [kk][bt])
__device__ float g_V  [BT*HD];   // 1 MB  (natural [bt][kk])
__device__ float g_Y  [BT*DM];   // 16 MB (tf32-rounded by flash epilogue)
__device__ float g_xr [BT*DM];   // 16 MB (x, tf32-rounded)
__device__ float g_Wqr[DM*DM];   // 4 MB  (Wq, tf32-rounded)
__device__ float g_Wor[DM*DM];   // 4 MB  (Wo, tf32-rounded)

// ---------------- helpers ----------------
__device__ __forceinline__ void fma2(u64& d, u64 a, u64 b){
    asm("fma.rn.f32x2 %0, %1, %2, %0;" : "+l"(d) : "l"(a), "l"(b));
}
__device__ __forceinline__ u64 dup2(float x){
    u64 r; asm("mov.b64 %0, {%1, %1};" : "=l"(r) : "f"(x)); return r;
}
__device__ __forceinline__ u64 mul2(u64 a, u64 b){
    u64 r; asm("mul.rn.f32x2 %0, %1, %2;" : "=l"(r) : "l"(a), "l"(b)); return r;
}
__device__ __forceinline__ float2 unpk(u64 v){
    float2 f; asm("mov.b64 {%0, %1}, %2;" : "=f"(f.x), "=f"(f.y) : "l"(v)); return f;
}
__device__ __forceinline__ float rtf32(float x){
    float r; asm("cvt.rna.tf32.f32 %0, %1;" : "=f"(r) : "f"(x)); return r;
}
__device__ __forceinline__ void cpasync16(uint32_t dst, const float* src){
    asm volatile("cp.async.cg.shared.global [%0], [%1], 16;" :: "r"(dst), "l"(src) : "memory");
}
__device__ __forceinline__ uint32_t smem_u32(const void* p){
    uint32_t a; asm("{ .reg .u64 t; cvta.to.shared.u64 t, %1; cvt.u32.u64 %0, t; }"
                    : "=r"(a) : "l"(p)); return a;
}

// ---------------- tf32 pre-round: dst[i] = round_tf32(src[i]) ---------------
__global__ __launch_bounds__(256)
void roundtf(const float* __restrict__ src, float* __restrict__ dst, int n4){
    int i = blockIdx.x * blockDim.x + threadIdx.x;
    if (i >= n4) return;
    float4 v = ((const float4*)src)[i];
    v.x = rtf32(v.x); v.y = rtf32(v.y); v.z = rtf32(v.z); v.w = rtf32(v.w);
    ((float4*)dst)[i] = v;
}

// ---------------- wmma tf32 GEMM: C[M,N] = A[M,K] @ B[K,N] ------------------
// Inputs MUST be tf32-pre-rounded. Block 128x128, BK=32, 4 warps, warp tile
// 64x64 = 4x4 m16n16k8 fragments. 2-stage cp.async pipeline. fp32 accum.
#define WLDA 36    // A tile leading dim (floats)
#define WLDB 132   // B tile leading dim (floats)
#define WSTAGE (128*WLDA + 32*WLDB)   // floats per stage = 8832

__global__ __launch_bounds__(128)
void wgemm(const float* __restrict__ A, const float* __restrict__ B,
           float* __restrict__ C, int M, int N, int K)
{
    extern __shared__ float ws[];
    float* As[2] = { ws,            ws + WSTAGE };
    float* Bs[2] = { ws + 128*WLDA, ws + WSTAGE + 128*WLDA };
    const uint32_t sbase = smem_u32(ws);

    const int tid = threadIdx.x;
    const int wid = tid >> 5;
    const int wm  = wid & 1;        // 0..1 : 64-row strip
    const int wn  = wid >> 1;       // 0..1 : 64-col strip
    const int rowBase = blockIdx.y * 128;
    const int colBase = blockIdx.x * 128;

    auto load_stage = [&](int it, int s){
        const int bk = it * 32;
        const uint32_t sa = sbase + (uint32_t)s * (WSTAGE*4u);
        // A tile: 128 rows x 32 floats -> 1024 16B chunks (8 per thread)
        #pragma unroll
        for (int i = 0; i < 8; ++i) {
            int c = tid + 128*i;
            int row = c >> 3, seg = c & 7;
            cpasync16(sa + (uint32_t)(row*WLDA + seg*4)*4u,
                      &A[(u64)(rowBase+row)*K + bk + seg*4]);
        }
        // B tile: 32 rows x 128 floats -> 1024 16B chunks (8 per thread)
        const uint32_t sbB = sa + 128u*WLDA*4u;
        #pragma unroll
        for (int i = 0; i < 8; ++i) {
            int c = tid + 128*i;
            int row = c >> 5, seg = c & 31;
            cpasync16(sbB + (uint32_t)(row*WLDB + seg*4)*4u,
                      &B[(u64)(bk+row)*N + colBase + seg*4]);
        }
        asm volatile("cp.async.commit_group;" ::: "memory");
    };

    wmma::fragment<wmma::accumulator, 16, 16, 8, float> acc[4][4];
    #pragma unroll
    for (int i = 0; i < 4; ++i)
        #pragma unroll
        for (int j = 0; j < 4; ++j)
            wmma::fill_fragment(acc[i][j], 0.0f);

    const int nIt = K / 32;
    load_stage(0, 0);
    load_stage(1, 1);

    for (int it = 0; it < nIt; ++it) {
        const int s = it & 1;
        if (it + 2 < nIt) asm volatile("cp.async.wait_group 1;" ::: "memory");
        else              asm volatile("cp.async.wait_group 0;" ::: "memory");
        __syncthreads();

        #pragma unroll
        for (int ks = 0; ks < 32; ks += 8) {
            wmma::fragment<wmma::matrix_a, 16, 16, 8, wmma::precision::tf32, wmma::row_major> af[4];
            wmma::fragment<wmma::matrix_b, 16, 16, 8, wmma::precision::tf32, wmma::row_major> bf[4];
            #pragma unroll
            for (int i = 0; i < 4; ++i)
                wmma::load_matrix_sync(af[i], &As[s][(wm*64 + i*16)*WLDA + ks], WLDA);
            #pragma unroll
            for (int j = 0; j < 4; ++j)
                wmma::load_matrix_sync(bf[j], &Bs[s][ks*WLDB + wn*64 + j*16], WLDB);
            #pragma unroll
            for (int i = 0; i < 4; ++i)
                #pragma unroll
                for (int j = 0; j < 4; ++j)
                    wmma::mma_sync(acc[i][j], af[i], bf[j], acc[i][j]);
        }
        __syncthreads();
        if (it + 2 < nIt) load_stage(it + 2, s);
    }

    #pragma unroll
    for (int i = 0; i < 4; ++i)
        #pragma unroll
        for (int j = 0; j < 4; ++j)
            wmma::store_matrix_sync(
                &C[(u64)(rowBase + wm*64 + i*16)*N + colBase + wn*64 + j*16],
                acc[i][j], N, wmma::mem_row_major);
}

// ---------------- scalar packed GEMM for small K/V projections --------------
template<int BM, int BN, int BK, int TM, int TN, bool TRANS>
__global__ __launch_bounds__(256)
void sgemm2(const float* __restrict__ A, const float* __restrict__ Bm,
            float* __restrict__ C, int M, int N, int K)
{
    __shared__ float As[BK*BM];
    __shared__ float Bs[BK*BN];

    const int tid = threadIdx.x;
    const int tc  = tid % (BN/TN);
    const int tr  = tid / (BN/TN);
    const int rowBase = blockIdx.y * BM;
    const int colBase = blockIdx.x * BN;

    const int irA = tid / (BK/4);
    const int icA = (tid % (BK/4)) * 4;
    constexpr int sA = (256*4)/BK;
    const int irB = tid / (BN/4);
    const int icB = (tid % (BN/4)) * 4;
    constexpr int sB = (256*4)/BN;

    u64 res2[TM*(TN/2)];
    #pragma unroll
    for (int i = 0; i < TM*(TN/2); ++i) res2[i] = 0ull;

    for (int bk = 0; bk < K; bk += BK) {
        #pragma unroll
        for (int off = 0; off < BM; off += sA) {
            float4 t = *(const float4*)&A[(rowBase+irA+off)*K + bk + icA];
            As[(icA+0)*BM + irA+off] = t.x;
            As[(icA+1)*BM + irA+off] = t.y;
            As[(icA+2)*BM + irA+off] = t.z;
            As[(icA+3)*BM + irA+off] = t.w;
        }
        #pragma unroll
        for (int off = 0; off < BK; off += sB)
            *(float4*)&Bs[(irB+off)*BN + icB] =
                *(const float4*)&Bm[(bk+irB+off)*N + colBase + icB];
        __syncthreads();

        #pragma unroll
        for (int kk = 0; kk < BK; ++kk) {
            float regM[TM]; u64 regN[TN/2];
            #pragma unroll
            for (int q = 0; q < TM/4; ++q)
                *(float4*)&regM[q*4] = *(const float4*)&As[kk*BM + tr*TM + q*4];
            #pragma unroll
            for (int q = 0; q < TN/4; ++q) {
                ulonglong2 t = *(const ulonglong2*)&Bs[kk*BN + tc*TN + q*4];
                regN[q*2] = t.x; regN[q*2+1] = t.y;
            }
            #pragma unroll
            for (int i = 0; i < TM; ++i) {
                u64 a = dup2(regM[i]);
                #pragma unroll
                for (int j = 0; j < TN/2; ++j) fma2(res2[i*(TN/2)+j], a, regN[j]);
            }
        }
        __syncthreads();
    }

    if (!TRANS) {
        #pragma unroll
        for (int i = 0; i < TM; ++i)
            #pragma unroll
            for (int jq = 0; jq < TN/4; ++jq) {
                float2 a = unpk(res2[i*(TN/2)+jq*2]);
                float2 b = unpk(res2[i*(TN/2)+jq*2+1]);
                *(float4*)&C[(rowBase+tr*TM+i)*N + colBase+tc*TN+jq*4] =
                    make_float4(a.x, a.y, b.x, b.y);
            }
    } else {
        float rs[TM*TN];
        #pragma unroll
        for (int i = 0; i < TM; ++i)
            #pragma unroll
            for (int j = 0; j < TN/2; ++j) {
                float2 a = unpk(res2[i*(TN/2)+j]);
                rs[i*TN + j*2] = a.x; rs[i*TN + j*2+1] = a.y;
            }
        #pragma unroll
        for (int j = 0; j < TN; ++j)
            #pragma unroll
            for (int iq = 0; iq < TM/4; ++iq)
                *(float4*)&C[(colBase+tc*TN+j)*M + rowBase+tr*TM+iq*4] =
                    make_float4(rs[(iq*4+0)*TN+j], rs[(iq*4+1)*TN+j],
                                rs[(iq*4+2)*TN+j], rs[(iq*4+3)*TN+j]);
    }
}

// ---------------- causal MQA flash attention (flash2) -----------------------
// Epilogue rounds Y to tf32 so the Wo wgemm can skip conversions.
__global__ __launch_bounds__(256)
void flash2(const float* __restrict__ Q, const float* __restrict__ Kt,
            const float* __restrict__ V, float* __restrict__ Y)
{
    extern __shared__ float smx[];
    float* Qt  = smx;             // [64][68]  kk-major Q (pre-scaled)
    float* KtP = smx + 64*68;     // [64][68]  kk-major K; reused as P^T
    float* Vs  = smx + 2*64*68;   // [64][68]  c-major V

    const int qt = blockIdx.x, h = blockIdx.y, b = blockIdx.z;
    const int tid = threadIdx.x;
    const int ty = tid >> 4, tx = tid & 15;
    const int rowQ0 = b*TS + qt*64;
    const int rowK0 = b*TS;

    #pragma unroll
    for (int p = 0; p < 4; ++p) {
        int lin = p*1024 + tid*4;
        int r = lin >> 6, d = lin & 63;
        float4 q = *(const float4*)&Q[(rowQ0+r)*DM + h*HD + d];
        Qt[(d+0)*68 + r] = q.x * 0.125f;
        Qt[(d+1)*68 + r] = q.y * 0.125f;
        Qt[(d+2)*68 + r] = q.z * 0.125f;
        Qt[(d+3)*68 + r] = q.w * 0.125f;
    }

    u64 acc2[8];
    #pragma unroll
    for (int i = 0; i < 8; ++i) acc2[i] = 0ull;
    float mprev[4], lsum[4];
    #pragma unroll
    for (int i = 0; i < 4; ++i) { mprev[i] = -1e30f; lsum[i] = 0.f; }

    for (int kt = 0; kt <= qt; ++kt) {
        __syncthreads();
        #pragma unroll
        for (int p = 0; p < 4; ++p) {
            int lin = p*1024 + tid*4;
            int a = lin >> 6, e = lin & 63;
            *(float4*)&KtP[a*68 + e] = *(const float4*)&Kt[a*BT + rowK0 + kt*64 + e];
            *(float4*)&Vs [a*68 + e] = *(const float4*)&V[(rowK0 + kt*64 + a)*HD + e];
        }
        __syncthreads();

        u64 s2[8];
        #pragma unroll
        for (int i = 0; i < 8; ++i) s2[i] = 0ull;
        #pragma unroll 16
        for (int kk = 0; kk < 64; ++kk) {
            float4 q4 = *(const float4*)&Qt[kk*68 + ty*4];
            ulonglong2 k2 = *(const ulonglong2*)&KtP[kk*68 + tx*4];
            u64 a0 = dup2(q4.x), a1 = dup2(q4.y), a2 = dup2(q4.z), a3 = dup2(q4.w);
            fma2(s2[0],a0,k2.x); fma2(s2[1],a0,k2.y);
            fma2(s2[2],a1,k2.x); fma2(s2[3],a1,k2.y);
            fma2(s2[4],a2,k2.x); fma2(s2[5],a2,k2.y);
            fma2(s2[6],a3,k2.x); fma2(s2[7],a3,k2.y);
        }

        float s[16];
        #pragma unroll
        for (int i = 0; i < 4; ++i) {
            float2 a = unpk(s2[i*2]), c = unpk(s2[i*2+1]);
            s[i*4+0]=a.x; s[i*4+1]=a.y; s[i*4+2]=c.x; s[i*4+3]=c.y;
        }

        if (kt == qt) {
            #pragma unroll
            for (int i = 0; i < 4; ++i)
                #pragma unroll
                for (int j = 0; j < 4; ++j)
                    if (tx*4+j > ty*4+i) s[i*4+j] = -1e30f;
        }

        #pragma unroll
        for (int i = 0; i < 4; ++i) {
            float mx = fmaxf(fmaxf(s[i*4],s[i*4+1]), fmaxf(s[i*4+2],s[i*4+3]));
            #pragma unroll
            for (int o = 8; o; o >>= 1) mx = fmaxf(mx, __shfl_xor_sync(0xffffffffu, mx, o));
            float mnew = fmaxf(mprev[i], mx);
            float sc   = __expf(mprev[i] - mnew);
            float rs = 0.f;
            #pragma unroll
            for (int j = 0; j < 4; ++j) { s[i*4+j] = __expf(s[i*4+j] - mnew); rs += s[i*4+j]; }
            #pragma unroll
            for (int o = 8; o; o >>= 1) rs += __shfl_xor_sync(0xffffffffu, rs, o);
            lsum[i]  = lsum[i]*sc + rs;
            mprev[i] = mnew;
            u64 sc2 = dup2(sc);
            acc2[i*2]   = mul2(acc2[i*2],   sc2);
            acc2[i*2+1] = mul2(acc2[i*2+1], sc2);
        }

        __syncthreads();
        #pragma unroll
        for (int j = 0; j < 4; ++j)
            #pragma unroll
            for (int i = 0; i < 4; ++i)
                KtP[(tx*4+j)*68 + ty*4+i] = s[i*4+j];
        __syncthreads();

        #pragma unroll 4
        for (int c = 0; c < 64; ++c) {
            float rp[4];
            #pragma unroll
            for (int i = 0; i < 4; ++i) rp[i] = KtP[c*68 + ty*4+i];
            ulonglong2 v2 = *(const ulonglong2*)&Vs[c*68 + tx*4];
            #pragma unroll
            for (int i = 0; i < 4; ++i) {
                u64 a = dup2(rp[i]);
                fma2(acc2[i*2],   a, v2.x);
                fma2(acc2[i*2+1], a, v2.y);
            }
        }
    }

    #pragma unroll
    for (int i = 0; i < 4; ++i) {
        float inv = 1.f / lsum[i];
        float2 a = unpk(acc2[i*2]), c = unpk(acc2[i*2+1]);
        *(float4*)&Y[(rowQ0+ty*4+i)*DM + h*HD + tx*4] =
            make_float4(rtf32(a.x*inv), rtf32(a.y*inv),
                        rtf32(c.x*inv), rtf32(c.y*inv));
    }
}

// ---------------- launch ----------------
extern "C" void kernel_launch(void* const* d_in, const int* in_sizes, int n_in,
                              void* d_out, int out_size) {
    const float* x  = (const float*)d_in[0];
    const float* Wq = (const float*)d_in[1];
    const float* Wk = (const float*)d_in[2];
    const float* Wv = (const float*)d_in[3];
    const float* Wo = (const float*)d_in[4];
    float* out = (float*)d_out;

    float *Qb, *Ktb, *Vb, *Yb, *xr, *Wqr, *Wor;
    cudaGetSymbolAddress((void**)&Qb,  g_Q);
    cudaGetSymbolAddress((void**)&Ktb, g_Kt);
    cudaGetSymbolAddress((void**)&Vb,  g_V);
    cudaGetSymbolAddress((void**)&Yb,  g_Y);
    cudaGetSymbolAddress((void**)&xr,  g_xr);
    cudaGetSymbolAddress((void**)&Wqr, g_Wqr);
    cudaGetSymbolAddress((void**)&Wor, g_Wor);

    const int fsm = 3 * 64 * 68 * (int)sizeof(float);   // 52224 B
    cudaFuncSetAttribute(flash2, cudaFuncAttributeMaxDynamicSharedMemorySize, fsm);
    const int gsm = 2 * WSTAGE * (int)sizeof(float);    // 70656 B
    cudaFuncSetAttribute(wgemm, cudaFuncAttributeMaxDynamicSharedMemorySize, gsm);

    // tf32 pre-round (x for Q-proj; weights for both wgemms)
    roundtf<<<(BT*DM/4 + 255)/256, 256>>>(x,  xr,  BT*DM/4);
    roundtf<<<(DM*DM/4 + 255)/256, 256>>>(Wq, Wqr, DM*DM/4);
    roundtf<<<(DM*DM/4 + 255)/256, 256>>>(Wo, Wor, DM*DM/4);

    // Q = x @ Wq  (wmma tf32, pre-rounded inputs)
    wgemm<<<dim3(DM/128, BT/128), 128, gsm>>>(xr, Wqr, Qb, BT, DM, DM);
    // K^T = (x @ Wk)^T  -> [64][4096]   (full fp32)
    sgemm2<64,64,16,4,4,true> <<<dim3(1, BT/64), 256>>>(x, Wk, Ktb, BT, HD, DM);
    // V = x @ Wv                        (full fp32)
    sgemm2<64,64,16,4,4,false><<<dim3(1, BT/64), 256>>>(x, Wv, Vb, BT, HD, DM);
    // causal MQA attention -> Y (tf32-rounded on write)
    flash2<<<dim3(TS/64, NH, 2), 256, fsm>>>(Qb, Ktb, Vb, Yb);
    // out = Y @ Wo  (wmma tf32, pre-rounded inputs)
    wgemm<<<dim3(DM/128, BT/128), 128, gsm>>>(Yb, Wor, out, BT, DM, DM);
}

// round 11
// speedup vs baseline: 1.4588x; 1.1161x over previous
#include <cuda_runtime.h>
#include <mma.h>
#include <cstdint>

using namespace nvcuda;
typedef unsigned long long u64;

#define BT 4096      // B*T
#define DM 1024
#define NH 16
#define HD 64
#define TS 2048

// ---------------- scratch ----------------
__device__ float g_Q  [BT*DM];   // 16 MB (natural [bt][d])
__device__ float g_Kt [HD*BT];   // 1 MB  (TRANSPOSED: [kk][bt])
__device__ float g_V  [BT*HD];   // 1 MB  (natural [bt][kk])
__device__ float g_Y  [BT*DM];   // 16 MB (tf32-rounded by flash epilogue)
__device__ float g_xr [BT*DM];   // 16 MB (x, tf32-rounded)
__device__ float g_Wqr[DM*DM];   // 4 MB  (Wq, tf32-rounded)
__device__ float g_Wor[DM*DM];   // 4 MB  (Wo, tf32-rounded)

// ---------------- helpers ----------------
__device__ __forceinline__ void fma2(u64& d, u64 a, u64 b){
    asm("fma.rn.f32x2 %0, %1, %2, %0;" : "+l"(d) : "l"(a), "l"(b));
}
__device__ __forceinline__ u64 dup2(float x){
    u64 r; asm("mov.b64 %0, {%1, %1};" : "=l"(r) : "f"(x)); return r;
}
__device__ __forceinline__ float2 unpk(u64 v){
    float2 f; asm("mov.b64 {%0, %1}, %2;" : "=f"(f.x), "=f"(f.y) : "l"(v)); return f;
}
__device__ __forceinline__ float rtf32(float x){
    float r; asm("cvt.rna.tf32.f32 %0, %1;" : "=f"(r) : "f"(x)); return r;
}
__device__ __forceinline__ void cpasync16(uint32_t dst, const float* src){
    asm volatile("cp.async.cg.shared.global [%0], [%1], 16;" :: "r"(dst), "l"(src) : "memory");
}
__device__ __forceinline__ uint32_t smem_u32(const void* p){
    uint32_t a; asm("{ .reg .u64 t; cvta.to.shared.u64 t, %1; cvt.u32.u64 %0, t; }"
                    : "=r"(a) : "l"(p)); return a;
}

// ---------------- tf32 pre-round ----------------
__global__ __launch_bounds__(256)
void roundtf(const float* __restrict__ src, float* __restrict__ dst, int n4){
    int i = blockIdx.x * blockDim.x + threadIdx.x;
    if (i >= n4) return;
    float4 v = ((const float4*)src)[i];
    v.x = rtf32(v.x); v.y = rtf32(v.y); v.z = rtf32(v.z); v.w = rtf32(v.w);
    ((float4*)dst)[i] = v;
}

// ---------------- wmma tf32 GEMM (unchanged from R10: 124.6us) --------------
#define WLDA 36
#define WLDB 132
#define WSTAGE (128*WLDA + 32*WLDB)

__global__ __launch_bounds__(128)
void wgemm(const float* __restrict__ A, const float* __restrict__ B,
           float* __restrict__ C, int M, int N, int K)
{
    extern __shared__ float ws[];
    float* As[2] = { ws,            ws + WSTAGE };
    float* Bs[2] = { ws + 128*WLDA, ws + WSTAGE + 128*WLDA };
    const uint32_t sbase = smem_u32(ws);

    const int tid = threadIdx.x;
    const int wid = tid >> 5;
    const int wm  = wid & 1;
    const int wn  = wid >> 1;
    const int rowBase = blockIdx.y * 128;
    const int colBase = blockIdx.x * 128;

    auto load_stage = [&](int it, int s){
        const int bk = it * 32;
        const uint32_t sa = sbase + (uint32_t)s * (WSTAGE*4u);
        #pragma unroll
        for (int i = 0; i < 8; ++i) {
            int c = tid + 128*i;
            int row = c >> 3, seg = c & 7;
            cpasync16(sa + (uint32_t)(row*WLDA + seg*4)*4u,
                      &A[(u64)(rowBase+row)*K + bk + seg*4]);
        }
        const uint32_t sbB = sa + 128u*WLDA*4u;
        #pragma unroll
        for (int i = 0; i < 8; ++i) {
            int c = tid + 128*i;
            int row = c >> 5, seg = c & 31;
            cpasync16(sbB + (uint32_t)(row*WLDB + seg*4)*4u,
                      &B[(u64)(bk+row)*N + colBase + seg*4]);
        }
        asm volatile("cp.async.commit_group;" ::: "memory");
    };

    wmma::fragment<wmma::accumulator, 16, 16, 8, float> acc[4][4];
    #pragma unroll
    for (int i = 0; i < 4; ++i)
        #pragma unroll
        for (int j = 0; j < 4; ++j)
            wmma::fill_fragment(acc[i][j], 0.0f);

    const int nIt = K / 32;
    load_stage(0, 0);
    load_stage(1, 1);

    for (int it = 0; it < nIt; ++it) {
        const int s = it & 1;
        if (it + 2 < nIt) asm volatile("cp.async.wait_group 1;" ::: "memory");
        else              asm volatile("cp.async.wait_group 0;" ::: "memory");
        __syncthreads();

        #pragma unroll
        for (int ks = 0; ks < 32; ks += 8) {
            wmma::fragment<wmma::matrix_a, 16, 16, 8, wmma::precision::tf32, wmma::row_major> af[4];
            wmma::fragment<wmma::matrix_b, 16, 16, 8, wmma::precision::tf32, wmma::row_major> bf[4];
            #pragma unroll
            for (int i = 0; i < 4; ++i)
                wmma::load_matrix_sync(af[i], &As[s][(wm*64 + i*16)*WLDA + ks], WLDA);
            #pragma unroll
            for (int j = 0; j < 4; ++j)
                wmma::load_matrix_sync(bf[j], &Bs[s][ks*WLDB + wn*64 + j*16], WLDB);
            #pragma unroll
            for (int i = 0; i < 4; ++i)
                #pragma unroll
                for (int j = 0; j < 4; ++j)
                    wmma::mma_sync(acc[i][j], af[i], bf[j], acc[i][j]);
        }
        __syncthreads();
        if (it + 2 < nIt) load_stage(it + 2, s);
    }

    #pragma unroll
    for (int i = 0; i < 4; ++i)
        #pragma unroll
        for (int j = 0; j < 4; ++j)
            wmma::store_matrix_sync(
                &C[(u64)(rowBase + wm*64 + i*16)*N + colBase + wn*64 + j*16],
                acc[i][j], N, wmma::mem_row_major);
}

// ---------------- scalar packed GEMM for small K/V projections --------------
template<int BM, int BN, int BK, int TM, int TN, bool TRANS>
__global__ __launch_bounds__(256)
void sgemm2(const float* __restrict__ A, const float* __restrict__ Bm,
            float* __restrict__ C, int M, int N, int K)
{
    __shared__ float As[BK*BM];
    __shared__ float Bs[BK*BN];

    const int tid = threadIdx.x;
    const int tc  = tid % (BN/TN);
    const int tr  = tid / (BN/TN);
    const int rowBase = blockIdx.y * BM;
    const int colBase = blockIdx.x * BN;

    const int irA = tid / (BK/4);
    const int icA = (tid % (BK/4)) * 4;
    constexpr int sA = (256*4)/BK;
    const int irB = tid / (BN/4);
    const int icB = (tid % (BN/4)) * 4;
    constexpr int sB = (256*4)/BN;

    u64 res2[TM*(TN/2)];
    #pragma unroll
    for (int i = 0; i < TM*(TN/2); ++i) res2[i] = 0ull;

    for (int bk = 0; bk < K; bk += BK) {
        #pragma unroll
        for (int off = 0; off < BM; off += sA) {
            float4 t = *(const float4*)&A[(rowBase+irA+off)*K + bk + icA];
            As[(icA+0)*BM + irA+off] = t.x;
            As[(icA+1)*BM + irA+off] = t.y;
            As[(icA+2)*BM + irA+off] = t.z;
            As[(icA+3)*BM + irA+off] = t.w;
        }
        #pragma unroll
        for (int off = 0; off < BK; off += sB)
            *(float4*)&Bs[(irB+off)*BN + icB] =
                *(const float4*)&Bm[(bk+irB+off)*N + colBase + icB];
        __syncthreads();

        #pragma unroll
        for (int kk = 0; kk < BK; ++kk) {
            float regM[TM]; u64 regN[TN/2];
            #pragma unroll
            for (int q = 0; q < TM/4; ++q)
                *(float4*)&regM[q*4] = *(const float4*)&As[kk*BM + tr*TM + q*4];
            #pragma unroll
            for (int q = 0; q < TN/4; ++q) {
                ulonglong2 t = *(const ulonglong2*)&Bs[kk*BN + tc*TN + q*4];
                regN[q*2] = t.x; regN[q*2+1] = t.y;
            }
            #pragma unroll
            for (int i = 0; i < TM; ++i) {
                u64 a = dup2(regM[i]);
                #pragma unroll
                for (int j = 0; j < TN/2; ++j) fma2(res2[i*(TN/2)+j], a, regN[j]);
            }
        }
        __syncthreads();
    }

    if (!TRANS) {
        #pragma unroll
        for (int i = 0; i < TM; ++i)
            #pragma unroll
            for (int jq = 0; jq < TN/4; ++jq) {
                float2 a = unpk(res2[i*(TN/2)+jq*2]);
                float2 b = unpk(res2[i*(TN/2)+jq*2+1]);
                *(float4*)&C[(rowBase+tr*TM+i)*N + colBase+tc*TN+jq*4] =
                    make_float4(a.x, a.y, b.x, b.y);
            }
    } else {
        float rs[TM*TN];
        #pragma unroll
        for (int i = 0; i < TM; ++i)
            #pragma unroll
            for (int j = 0; j < TN/2; ++j) {
                float2 a = unpk(res2[i*(TN/2)+j]);
                rs[i*TN + j*2] = a.x; rs[i*TN + j*2+1] = a.y;
            }
        #pragma unroll
        for (int j = 0; j < TN; ++j)
            #pragma unroll
            for (int iq = 0; iq < TM/4; ++iq)
                *(float4*)&C[(colBase+tc*TN+j)*M + rowBase+tr*TM+iq*4] =
                    make_float4(rs[(iq*4+0)*TN+j], rs[(iq*4+1)*TN+j],
                                rs[(iq*4+2)*TN+j], rs[(iq*4+3)*TN+j]);
    }
}

// ---------------- flash4: wmma-tf32 causal MQA flash attention --------------
// Grid: (16 q-tiles[128 rows], 16 heads, 2 batches), 256 threads / 8 warps.
// Warp grid 4(m)x2(n), 32x32 patches of 2x2 m16n16k8 frags. Per kv tile (64):
// S=Q@K^T (wmma) -> smem -> split-row online softmax -> P (wmma) @ V -> smem
// -> per-thread O regs (half-row, 32 floats). KS buffer = K tile / S / P / PV.
__global__ __launch_bounds__(256, 2)
void flash4(const float* __restrict__ Q, const float* __restrict__ Kt,
            const float* __restrict__ V, float* __restrict__ Y)
{
    extern __shared__ float smx[];
    float* Qs   = smx;                 // [128][68] q rows (pre-scaled, tf32)
    float* KS   = smx + 128*68;        // [128][68] K^T tile (rows 0..63) / S / P / PV
    float* Vs   = smx + 2*128*68;      // [64][68]  V tile [c][d]
    float* sred = smx + 2*128*68 + 64*68;  // [256] cross-half reduce scratch

    const int qt = (int)(gridDim.x - 1) - (int)blockIdx.x;   // heavy tiles first
    const int h  = blockIdx.y, b = blockIdx.z;
    const int tid = threadIdx.x;
    const int wid = tid >> 5;
    const int wm  = wid & 3;        // m strip (32 q-rows)
    const int wn  = wid >> 2;       // n strip (32 cols)
    const int r   = tid & 127;      // owned q-row
    const int hf  = tid >> 7;       // owned half (cols hf*32..+31)
    const int rowQ0 = b*TS + qt*128;
    const int rowK0 = b*TS;
    const int qr    = qt*128 + r;   // within-sequence q row

    // Load Q tile (scaled by 1/8, tf32-rounded)
    #pragma unroll
    for (int p = 0; p < 8; ++p) {
        int lin = p*1024 + tid*4;
        int rr = lin >> 6, d = lin & 63;
        float4 q = *(const float4*)&Q[(u64)(rowQ0+rr)*DM + h*HD + d];
        *(float4*)&Qs[rr*68 + d] = make_float4(rtf32(q.x*0.125f), rtf32(q.y*0.125f),
                                               rtf32(q.z*0.125f), rtf32(q.w*0.125f));
    }

    float O[32];
    #pragma unroll
    for (int i = 0; i < 32; ++i) O[i] = 0.f;
    float mprev = -1e30f, lsum = 0.f;

    const int nkv = 2*qt + 2;
    for (int kt = 0; kt < nkv; ++kt) {
        const int colK0 = kt*64;
        __syncthreads();   // prev iter done reading KS/Vs; Qs visible on iter 0
        // K tile [d][c] (from pre-transposed global) and V tile [c][d], tf32
        #pragma unroll
        for (int p = 0; p < 4; ++p) {
            int lin = p*1024 + tid*4;
            int a = lin >> 6, e = lin & 63;
            float4 k4 = *(const float4*)&Kt[(u64)a*BT + rowK0 + colK0 + e];
            *(float4*)&KS[a*68 + e] = make_float4(rtf32(k4.x), rtf32(k4.y),
                                                  rtf32(k4.z), rtf32(k4.w));
            float4 v4 = *(const float4*)&V[(u64)(rowK0 + colK0 + a)*HD + e];
            *(float4*)&Vs[a*68 + e] = make_float4(rtf32(v4.x), rtf32(v4.y),
                                                  rtf32(v4.z), rtf32(v4.w));
        }
        __syncthreads();

        // ---- S = Q @ K^T ----
        wmma::fragment<wmma::accumulator, 16, 16, 8, float> sa[2][2];
        #pragma unroll
        for (int i = 0; i < 2; ++i)
            #pragma unroll
            for (int j = 0; j < 2; ++j) wmma::fill_fragment(sa[i][j], 0.f);
        #pragma unroll
        for (int ks = 0; ks < 8; ++ks) {
            wmma::fragment<wmma::matrix_a, 16, 16, 8, wmma::precision::tf32, wmma::row_major> af[2];
            wmma::fragment<wmma::matrix_b, 16, 16, 8, wmma::precision::tf32, wmma::row_major> bf[2];
            #pragma unroll
            for (int i = 0; i < 2; ++i)
                wmma::load_matrix_sync(af[i], &Qs[(wm*32 + i*16)*68 + ks*8], 68);
            #pragma unroll
            for (int j = 0; j < 2; ++j)
                wmma::load_matrix_sync(bf[j], &KS[(ks*8)*68 + wn*32 + j*16], 68);
            #pragma unroll
            for (int i = 0; i < 2; ++i)
                #pragma unroll
                for (int j = 0; j < 2; ++j)
                    wmma::mma_sync(sa[i][j], af[i], bf[j], sa[i][j]);
        }
        __syncthreads();   // all K-frag reads done before overwriting KS with S
        #pragma unroll
        for (int i = 0; i < 2; ++i)
            #pragma unroll
            for (int j = 0; j < 2; ++j)
                wmma::store_matrix_sync(&KS[(wm*32+i*16)*68 + wn*32 + j*16],
                                        sa[i][j], 68, wmma::mem_row_major);
        __syncthreads();

        // ---- online softmax (thread owns row r, cols hf*32..+31) ----
        float4 sv[8];
        #pragma unroll
        for (int q = 0; q < 8; ++q) sv[q] = *(float4*)&KS[r*68 + hf*32 + q*4];
        float* sp = (float*)sv;
        const int cb = colK0 + hf*32;
        #pragma unroll
        for (int j = 0; j < 32; ++j) if (cb + j > qr) sp[j] = -1e30f;
        float mloc = sp[0];
        #pragma unroll
        for (int j = 1; j < 32; ++j) mloc = fmaxf(mloc, sp[j]);
        sred[tid] = mloc;
        __syncthreads();
        float mnew = fmaxf(mprev, fmaxf(sred[r], sred[r+128]));
        float sc   = __expf(mprev - mnew);
        float ps = 0.f;
        #pragma unroll
        for (int j = 0; j < 32; ++j) { sp[j] = __expf(sp[j] - mnew); ps += sp[j]; }
        __syncthreads();   // all reads of sred(max) done
        sred[tid] = ps;
        // write P (tf32-rounded) back while waiting
        #pragma unroll
        for (int q = 0; q < 8; ++q) {
            float4 t = sv[q];
            *(float4*)&KS[r*68 + hf*32 + q*4] =
                make_float4(rtf32(t.x), rtf32(t.y), rtf32(t.z), rtf32(t.w));
        }
        #pragma unroll
        for (int j = 0; j < 32; ++j) O[j] *= sc;
        __syncthreads();
        lsum = lsum*sc + sred[r] + sred[r+128];
        mprev = mnew;

        // ---- O += P @ V ----
        wmma::fragment<wmma::accumulator, 16, 16, 8, float> pa[2][2];
        #pragma unroll
        for (int i = 0; i < 2; ++i)
            #pragma unroll
            for (int j = 0; j < 2; ++j) wmma::fill_fragment(pa[i][j], 0.f);
        #pragma unroll
        for (int ks = 0; ks < 8; ++ks) {
            wmma::fragment<wmma::matrix_a, 16, 16, 8, wmma::precision::tf32, wmma::row_major> af[2];
            wmma::fragment<wmma::matrix_b, 16, 16, 8, wmma::precision::tf32, wmma::row_major> bf[2];
            #pragma unroll
            for (int i = 0; i < 2; ++i)
                wmma::load_matrix_sync(af[i], &KS[(wm*32 + i*16)*68 + ks*8], 68);
            #pragma unroll
            for (int j = 0; j < 2; ++j)
                wmma::load_matrix_sync(bf[j], &Vs[(ks*8)*68 + wn*32 + j*16], 68);
            #pragma unroll
            for (int i = 0; i < 2; ++i)
                #pragma unroll
                for (int j = 0; j < 2; ++j)
                    wmma::mma_sync(pa[i][j], af[i], bf[j], pa[i][j]);
        }
        __syncthreads();   // all P-frag reads done before overwriting KS with PV
        #pragma unroll
        for (int i = 0; i < 2; ++i)
            #pragma unroll
            for (int j = 0; j < 2; ++j)
                wmma::store_matrix_sync(&KS[(wm*32+i*16)*68 + wn*32 + j*16],
                                        pa[i][j], 68, wmma::mem_row_major);
        __syncthreads();
        #pragma unroll
        for (int q = 0; q < 8; ++q) {
            float4 t = *(float4*)&KS[r*68 + hf*32 + q*4];
            O[q*4+0] += t.x; O[q*4+1] += t.y; O[q*4+2] += t.z; O[q*4+3] += t.w;
        }
    }

    // Normalize + write Y (tf32-rounded for the Wo wgemm)
    const float inv = 1.f / lsum;
    #pragma unroll
    for (int q = 0; q < 8; ++q) {
        *(float4*)&Y[(u64)(rowQ0 + r)*DM + h*HD + hf*32 + q*4] =
            make_float4(rtf32(O[q*4+0]*inv), rtf32(O[q*4+1]*inv),
                        rtf32(O[q*4+2]*inv), rtf32(O[q*4+3]*inv));
    }
}

// ---------------- launch ----------------
extern "C" void kernel_launch(void* const* d_in, const int* in_sizes, int n_in,
                              void* d_out, int out_size) {
    const float* x  = (const float*)d_in[0];
    const float* Wq = (const float*)d_in[1];
    const float* Wk = (const float*)d_in[2];
    const float* Wv = (const float*)d_in[3];
    const float* Wo = (const float*)d_in[4];
    float* out = (float*)d_out;

    float *Qb, *Ktb, *Vb, *Yb, *xr, *Wqr, *Wor;
    cudaGetSymbolAddress((void**)&Qb,  g_Q);
    cudaGetSymbolAddress((void**)&Ktb, g_Kt);
    cudaGetSymbolAddress((void**)&Vb,  g_V);
    cudaGetSymbolAddress((void**)&Yb,  g_Y);
    cudaGetSymbolAddress((void**)&xr,  g_xr);
    cudaGetSymbolAddress((void**)&Wqr, g_Wqr);
    cudaGetSymbolAddress((void**)&Wor, g_Wor);

    const int fsm = (2*128*68 + 64*68 + 256) * (int)sizeof(float);  // 88064 B
    cudaFuncSetAttribute(flash4, cudaFuncAttributeMaxDynamicSharedMemorySize, fsm);
    const int gsm = 2 * WSTAGE * (int)sizeof(float);                // 70656 B
    cudaFuncSetAttribute(wgemm, cudaFuncAttributeMaxDynamicSharedMemorySize, gsm);

    // tf32 pre-round (x for Q-proj; weights for both wgemms)
    roundtf<<<(BT*DM/4 + 255)/256, 256>>>(x,  xr,  BT*DM/4);
    roundtf<<<(DM*DM/4 + 255)/256, 256>>>(Wq, Wqr, DM*DM/4);
    roundtf<<<(DM*DM/4 + 255)/256, 256>>>(Wo, Wor, DM*DM/4);

    // Q = x @ Wq  (wmma tf32)
    wgemm<<<dim3(DM/128, BT/128), 128, gsm>>>(xr, Wqr, Qb, BT, DM, DM);
    // K^T = (x @ Wk)^T -> [64][4096]   (fp32)
    sgemm2<64,64,16,4,4,true> <<<dim3(1, BT/64), 256>>>(x, Wk, Ktb, BT, HD, DM);
    // V = x @ Wv                       (fp32)
    sgemm2<64,64,16,4,4,false><<<dim3(1, BT/64), 256>>>(x, Wv, Vb, BT, HD, DM);
    // causal MQA attention -> Y (wmma tf32)
    flash4<<<dim3(TS/128, NH, 2), 256, fsm>>>(Qb, Ktb, Vb, Yb);
    // out = Y @ Wo  (wmma tf32)
    wgemm<<<dim3(DM/128, BT/128), 128, gsm>>>(Yb, Wor, out, BT, DM, DM);
}

// round 12
// speedup vs baseline: 2.2023x; 1.5097x over previous
#include <cuda_runtime.h>
#include <mma.h>
#include <cstdint>

using namespace nvcuda;
typedef unsigned long long u64;

#define BT 4096      // B*T
#define DM 1024
#define NH 16
#define HD 64
#define TS 2048

// ---------------- scratch ----------------
__device__ float g_Q  [BT*DM];   // 16 MB (natural [bt][d])
__device__ float g_Kt [HD*BT];   // 1 MB  (TRANSPOSED [kk][bt], tf32-rounded)
__device__ float g_V  [BT*HD];   // 1 MB  (natural [bt][kk], tf32-rounded)
__device__ float g_Y  [BT*DM];   // 16 MB (tf32-rounded by flash epilogue)
__device__ float g_xr [BT*DM];   // 16 MB (x, tf32-rounded)
__device__ float g_Wqr[DM*DM];   // 4 MB
__device__ float g_Wor[DM*DM];   // 4 MB

// ---------------- helpers ----------------
__device__ __forceinline__ void fma2(u64& d, u64 a, u64 b){
    asm("fma.rn.f32x2 %0, %1, %2, %0;" : "+l"(d) : "l"(a), "l"(b));
}
__device__ __forceinline__ u64 dup2(float x){
    u64 r; asm("mov.b64 %0, {%1, %1};" : "=l"(r) : "f"(x)); return r;
}
__device__ __forceinline__ float2 unpk(u64 v){
    float2 f; asm("mov.b64 {%0, %1}, %2;" : "=f"(f.x), "=f"(f.y) : "l"(v)); return f;
}
__device__ __forceinline__ float rtf32(float x){
    float r; asm("cvt.rna.tf32.f32 %0, %1;" : "=f"(r) : "f"(x)); return r;
}
__device__ __forceinline__ void cpasync16(uint32_t dst, const float* src){
    asm volatile("cp.async.cg.shared.global [%0], [%1], 16;" :: "r"(dst), "l"(src) : "memory");
}
__device__ __forceinline__ uint32_t smem_u32(const void* p){
    uint32_t a; asm("{ .reg .u64 t; cvta.to.shared.u64 t, %1; cvt.u32.u64 %0, t; }"
                    : "=r"(a) : "l"(p)); return a;
}
// m16n8k8 tf32 mma, D += A*B (D aliases C)
__device__ __forceinline__ void mma8(float* d, const uint32_t* a, uint32_t b0, uint32_t b1){
    asm volatile("mma.sync.aligned.m16n8k8.row.col.f32.tf32.tf32.f32 "
        "{%0,%1,%2,%3}, {%4,%5,%6,%7}, {%8,%9}, {%0,%1,%2,%3};"
        : "+f"(d[0]), "+f"(d[1]), "+f"(d[2]), "+f"(d[3])
        : "r"(a[0]), "r"(a[1]), "r"(a[2]), "r"(a[3]), "r"(b0), "r"(b1));
}

// ---------------- tf32 pre-round ----------------
__global__ __launch_bounds__(256)
void roundtf(const float* __restrict__ src, float* __restrict__ dst, int n4){
    int i = blockIdx.x * blockDim.x + threadIdx.x;
    if (i >= n4) return;
    float4 v = ((const float4*)src)[i];
    v.x = rtf32(v.x); v.y = rtf32(v.y); v.z = rtf32(v.z); v.w = rtf32(v.w);
    ((float4*)dst)[i] = v;
}

// ---------------- wmma tf32 GEMM (unchanged: 124.6us) -----------------------
#define WLDA 36
#define WLDB 132
#define WSTAGE (128*WLDA + 32*WLDB)

__global__ __launch_bounds__(128)
void wgemm(const float* __restrict__ A, const float* __restrict__ B,
           float* __restrict__ C, int M, int N, int K)
{
    extern __shared__ float ws[];
    float* As[2] = { ws,            ws + WSTAGE };
    float* Bs[2] = { ws + 128*WLDA, ws + WSTAGE + 128*WLDA };
    const uint32_t sbase = smem_u32(ws);

    const int tid = threadIdx.x;
    const int wid = tid >> 5;
    const int wm  = wid & 1;
    const int wn  = wid >> 1;
    const int rowBase = blockIdx.y * 128;
    const int colBase = blockIdx.x * 128;

    auto load_stage = [&](int it, int s){
        const int bk = it * 32;
        const uint32_t sa = sbase + (uint32_t)s * (WSTAGE*4u);
        #pragma unroll
        for (int i = 0; i < 8; ++i) {
            int c = tid + 128*i;
            int row = c >> 3, seg = c & 7;
            cpasync16(sa + (uint32_t)(row*WLDA + seg*4)*4u,
                      &A[(u64)(rowBase+row)*K + bk + seg*4]);
        }
        const uint32_t sbB = sa + 128u*WLDA*4u;
        #pragma unroll
        for (int i = 0; i < 8; ++i) {
            int c = tid + 128*i;
            int row = c >> 5, seg = c & 31;
            cpasync16(sbB + (uint32_t)(row*WLDB + seg*4)*4u,
                      &B[(u64)(bk+row)*N + colBase + seg*4]);
        }
        asm volatile("cp.async.commit_group;" ::: "memory");
    };

    wmma::fragment<wmma::accumulator, 16, 16, 8, float> acc[4][4];
    #pragma unroll
    for (int i = 0; i < 4; ++i)
        #pragma unroll
        for (int j = 0; j < 4; ++j)
            wmma::fill_fragment(acc[i][j], 0.0f);

    const int nIt = K / 32;
    load_stage(0, 0);
    load_stage(1, 1);

    for (int it = 0; it < nIt; ++it) {
        const int s = it & 1;
        if (it + 2 < nIt) asm volatile("cp.async.wait_group 1;" ::: "memory");
        else              asm volatile("cp.async.wait_group 0;" ::: "memory");
        __syncthreads();

        #pragma unroll
        for (int ks = 0; ks < 32; ks += 8) {
            wmma::fragment<wmma::matrix_a, 16, 16, 8, wmma::precision::tf32, wmma::row_major> af[4];
            wmma::fragment<wmma::matrix_b, 16, 16, 8, wmma::precision::tf32, wmma::row_major> bf[4];
            #pragma unroll
            for (int i = 0; i < 4; ++i)
                wmma::load_matrix_sync(af[i], &As[s][(wm*64 + i*16)*WLDA + ks], WLDA);
            #pragma unroll
            for (int j = 0; j < 4; ++j)
                wmma::load_matrix_sync(bf[j], &Bs[s][ks*WLDB + wn*64 + j*16], WLDB);
            #pragma unroll
            for (int i = 0; i < 4; ++i)
                #pragma unroll
                for (int j = 0; j < 4; ++j)
                    wmma::mma_sync(acc[i][j], af[i], bf[j], acc[i][j]);
        }
        __syncthreads();
        if (it + 2 < nIt) load_stage(it + 2, s);
    }

    #pragma unroll
    for (int i = 0; i < 4; ++i)
        #pragma unroll
        for (int j = 0; j < 4; ++j)
            wmma::store_matrix_sync(
                &C[(u64)(rowBase + wm*64 + i*16)*N + colBase + wn*64 + j*16],
                acc[i][j], N, wmma::mem_row_major);
}

// ---------------- scalar packed GEMM for small K/V projections --------------
// R: tf32-round outputs (K/V feed tensor-core attention).
template<int BM, int BN, int BK, int TM, int TN, bool TRANS, bool R>
__global__ __launch_bounds__(256)
void sgemm2(const float* __restrict__ A, const float* __restrict__ Bm,
            float* __restrict__ C, int M, int N, int K)
{
    __shared__ float As[BK*BM];
    __shared__ float Bs[BK*BN];

    const int tid = threadIdx.x;
    const int tc  = tid % (BN/TN);
    const int tr  = tid / (BN/TN);
    const int rowBase = blockIdx.y * BM;
    const int colBase = blockIdx.x * BN;

    const int irA = tid / (BK/4);
    const int icA = (tid % (BK/4)) * 4;
    constexpr int sA = (256*4)/BK;
    const int irB = tid / (BN/4);
    const int icB = (tid % (BN/4)) * 4;
    constexpr int sB = (256*4)/BN;

    u64 res2[TM*(TN/2)];
    #pragma unroll
    for (int i = 0; i < TM*(TN/2); ++i) res2[i] = 0ull;

    for (int bk = 0; bk < K; bk += BK) {
        #pragma unroll
        for (int off = 0; off < BM; off += sA) {
            float4 t = *(const float4*)&A[(rowBase+irA+off)*K + bk + icA];
            As[(icA+0)*BM + irA+off] = t.x;
            As[(icA+1)*BM + irA+off] = t.y;
            As[(icA+2)*BM + irA+off] = t.z;
            As[(icA+3)*BM + irA+off] = t.w;
        }
        #pragma unroll
        for (int off = 0; off < BK; off += sB)
            *(float4*)&Bs[(irB+off)*BN + icB] =
                *(const float4*)&Bm[(bk+irB+off)*N + colBase + icB];
        __syncthreads();

        #pragma unroll
        for (int kk = 0; kk < BK; ++kk) {
            float regM[TM]; u64 regN[TN/2];
            #pragma unroll
            for (int q = 0; q < TM/4; ++q)
                *(float4*)&regM[q*4] = *(const float4*)&As[kk*BM + tr*TM + q*4];
            #pragma unroll
            for (int q = 0; q < TN/4; ++q) {
                ulonglong2 t = *(const ulonglong2*)&Bs[kk*BN + tc*TN + q*4];
                regN[q*2] = t.x; regN[q*2+1] = t.y;
            }
            #pragma unroll
            for (int i = 0; i < TM; ++i) {
                u64 a = dup2(regM[i]);
                #pragma unroll
                for (int j = 0; j < TN/2; ++j) fma2(res2[i*(TN/2)+j], a, regN[j]);
            }
        }
        __syncthreads();
    }

    if (!TRANS) {
        #pragma unroll
        for (int i = 0; i < TM; ++i)
            #pragma unroll
            for (int jq = 0; jq < TN/4; ++jq) {
                float2 a = unpk(res2[i*(TN/2)+jq*2]);
                float2 b = unpk(res2[i*(TN/2)+jq*2+1]);
                float4 o = make_float4(a.x, a.y, b.x, b.y);
                if (R) { o.x=rtf32(o.x); o.y=rtf32(o.y); o.z=rtf32(o.z); o.w=rtf32(o.w); }
                *(float4*)&C[(rowBase+tr*TM+i)*N + colBase+tc*TN+jq*4] = o;
            }
    } else {
        float rs[TM*TN];
        #pragma unroll
        for (int i = 0; i < TM; ++i)
            #pragma unroll
            for (int j = 0; j < TN/2; ++j) {
                float2 a = unpk(res2[i*(TN/2)+j]);
                rs[i*TN + j*2] = a.x; rs[i*TN + j*2+1] = a.y;
            }
        #pragma unroll
        for (int j = 0; j < TN; ++j)
            #pragma unroll
            for (int iq = 0; iq < TM/4; ++iq) {
                float4 o = make_float4(rs[(iq*4+0)*TN+j], rs[(iq*4+1)*TN+j],
                                       rs[(iq*4+2)*TN+j], rs[(iq*4+3)*TN+j]);
                if (R) { o.x=rtf32(o.x); o.y=rtf32(o.y); o.z=rtf32(o.z); o.w=rtf32(o.w); }
                *(float4*)&C[(colBase+tc*TN+j)*M + rowBase+tr*TM+iq*4] = o;
            }
    }
}

// ---------------- flash5: register-resident PTX-mma flash attention ---------
// Grid (16 q-tiles, 16 heads, 2 batch), 256 thr / 8 warps; warp w owns q-rows
// w*16..+15. KV tile 64, double-buffered cp.async. Q as resident A-frags, O as
// resident accum frags, softmax on regs (documented m16n8k8 layouts), P via
// warp-private smem (syncwarp only). 2 __syncthreads per kv iter.
#define TILEF (64*72)     // floats per K or V tile (ld=72)
__global__ __launch_bounds__(256)
void flash5(const float* __restrict__ Q, const float* __restrict__ Kt,
            const float* __restrict__ V, float* __restrict__ Y)
{
    extern __shared__ float smx[];
    // [0, 4*TILEF): stage0 K,V | stage1 K,V ; then 8 x (16*68) P scratch
    const uint32_t sbase = smem_u32(smx);

    const int qt = (int)(gridDim.x - 1) - (int)blockIdx.x;   // heavy first
    const int h  = blockIdx.y, b = blockIdx.z;
    const int tid = threadIdx.x;
    const int w   = tid >> 5;
    const int lane = tid & 31;
    const int gid = lane >> 2;      // group id (row within frag)
    const int tig = lane & 3;       // thread in group
    const int rowQ0 = b*TS + qt*128;
    const int rowK0 = b*TS;
    const int qr0 = qt*128 + w*16 + gid;   // this thread's rows (and +8)
    const int nkv = 2*qt + 2;

    float* Pw = smx + 4*TILEF + w*(16*68);   // warp-private P scratch

    auto load_kv = [&](int kt, int s){
        const int colK0 = kt*64;
        const uint32_t ka = sbase + (uint32_t)s*(2*TILEF*4u);
        const uint32_t va = ka + TILEF*4u;
        #pragma unroll
        for (int i = 0; i < 4; ++i) {
            int c = tid + 256*i;          // 0..1023
            int row = c >> 4, seg = c & 15;
            cpasync16(ka + (uint32_t)(row*72 + seg*4)*4u,
                      &Kt[(u64)row*BT + rowK0 + colK0 + seg*4]);
            cpasync16(va + (uint32_t)(row*72 + seg*4)*4u,
                      &V[(u64)(rowK0 + colK0 + row)*HD + seg*4]);
        }
        asm volatile("cp.async.commit_group;" ::: "memory");
    };

    load_kv(0, 0);
    if (nkv > 1) load_kv(1, 1);

    // Resident Q A-frags (scaled by 1/8, tf32)
    uint32_t qa[8][4];
    {
        const float* qp = &Q[(u64)(rowQ0 + w*16 + gid)*DM + h*HD + tig];
        const float* qp8 = qp + 8*DM;
        #pragma unroll
        for (int kf = 0; kf < 8; ++kf) {
            qa[kf][0] = __float_as_uint(rtf32(0.125f * qp [kf*8]));
            qa[kf][1] = __float_as_uint(rtf32(0.125f * qp8[kf*8]));
            qa[kf][2] = __float_as_uint(rtf32(0.125f * qp [kf*8 + 4]));
            qa[kf][3] = __float_as_uint(rtf32(0.125f * qp8[kf*8 + 4]));
        }
    }

    float od[8][4];
    #pragma unroll
    for (int j = 0; j < 8; ++j)
        #pragma unroll
        for (int k = 0; k < 4; ++k) od[j][k] = 0.f;
    float m0 = -1e30f, m1 = -1e30f, l0 = 0.f, l1 = 0.f;

    for (int kt = 0; kt < nkv; ++kt) {
        const int s = kt & 1;
        if (kt + 1 < nkv) asm volatile("cp.async.wait_group 1;" ::: "memory");
        else              asm volatile("cp.async.wait_group 0;" ::: "memory");
        __syncthreads();
        const float* Ks = smx + s*(2*TILEF);
        const float* Vs = Ks + TILEF;

        // ---- S = Q @ K^T (16x64 per warp) ----
        float sd[8][4];
        #pragma unroll
        for (int j = 0; j < 8; ++j)
            #pragma unroll
            for (int k = 0; k < 4; ++k) sd[j][k] = 0.f;
        #pragma unroll
        for (int kf = 0; kf < 8; ++kf) {
            const float* Kr0 = Ks + (kf*8 + tig)*72;
            const float* Kr1 = Kr0 + 4*72;
            #pragma unroll
            for (int j = 0; j < 8; ++j)
                mma8(sd[j], qa[kf],
                     __float_as_uint(Kr0[j*8 + gid]),
                     __float_as_uint(Kr1[j*8 + gid]));
        }

        // ---- causal mask (only tiles that can touch the diagonal) ----
        const int colB = kt*64 + tig*2;
        if (kt*64 + 63 > qr0) {
            #pragma unroll
            for (int j = 0; j < 8; ++j) {
                int c0 = colB + j*8;
                if (c0     > qr0)   sd[j][0] = -1e30f;
                if (c0 + 1 > qr0)   sd[j][1] = -1e30f;
                if (c0     > qr0+8) sd[j][2] = -1e30f;
                if (c0 + 1 > qr0+8) sd[j][3] = -1e30f;
            }
        }

        // ---- online softmax on registers ----
        float mx0 = sd[0][0], mx1 = sd[0][2];
        #pragma unroll
        for (int j = 0; j < 8; ++j) {
            mx0 = fmaxf(mx0, fmaxf(sd[j][0], sd[j][1]));
            mx1 = fmaxf(mx1, fmaxf(sd[j][2], sd[j][3]));
        }
        mx0 = fmaxf(mx0, __shfl_xor_sync(0xffffffffu, mx0, 1));
        mx0 = fmaxf(mx0, __shfl_xor_sync(0xffffffffu, mx0, 2));
        mx1 = fmaxf(mx1, __shfl_xor_sync(0xffffffffu, mx1, 1));
        mx1 = fmaxf(mx1, __shfl_xor_sync(0xffffffffu, mx1, 2));
        float mn0 = fmaxf(m0, mx0), mn1 = fmaxf(m1, mx1);
        float sc0 = __expf(m0 - mn0), sc1 = __expf(m1 - mn1);
        float ps0 = 0.f, ps1 = 0.f;
        #pragma unroll
        for (int j = 0; j < 8; ++j) {
            sd[j][0] = __expf(sd[j][0] - mn0); ps0 += sd[j][0];
            sd[j][1] = __expf(sd[j][1] - mn0); ps0 += sd[j][1];
            sd[j][2] = __expf(sd[j][2] - mn1); ps1 += sd[j][2];
            sd[j][3] = __expf(sd[j][3] - mn1); ps1 += sd[j][3];
        }
        ps0 += __shfl_xor_sync(0xffffffffu, ps0, 1);
        ps0 += __shfl_xor_sync(0xffffffffu, ps0, 2);
        ps1 += __shfl_xor_sync(0xffffffffu, ps1, 1);
        ps1 += __shfl_xor_sync(0xffffffffu, ps1, 2);
        l0 = l0*sc0 + ps0; l1 = l1*sc1 + ps1;
        m0 = mn0; m1 = mn1;
        #pragma unroll
        for (int j = 0; j < 8; ++j) {
            od[j][0] *= sc0; od[j][1] *= sc0;
            od[j][2] *= sc1; od[j][3] *= sc1;
        }

        // ---- P: C-layout -> A-layout via warp-private scratch ----
        __syncwarp();
        #pragma unroll
        for (int j = 0; j < 8; ++j) {
            *(float2*)&Pw[ gid   *68 + j*8 + tig*2] =
                make_float2(rtf32(sd[j][0]), rtf32(sd[j][1]));
            *(float2*)&Pw[(gid+8)*68 + j*8 + tig*2] =
                make_float2(rtf32(sd[j][2]), rtf32(sd[j][3]));
        }
        __syncwarp();

        // ---- O += P @ V ----
        #pragma unroll
        for (int kf = 0; kf < 8; ++kf) {
            uint32_t pa[4];
            pa[0] = __float_as_uint(Pw[ gid   *68 + kf*8 + tig]);
            pa[1] = __float_as_uint(Pw[(gid+8)*68 + kf*8 + tig]);
            pa[2] = __float_as_uint(Pw[ gid   *68 + kf*8 + tig + 4]);
            pa[3] = __float_as_uint(Pw[(gid+8)*68 + kf*8 + tig + 4]);
            const float* Vr0 = Vs + (kf*8 + tig)*72;
            const float* Vr1 = Vr0 + 4*72;
            #pragma unroll
            for (int j = 0; j < 8; ++j)
                mma8(od[j], pa,
                     __float_as_uint(Vr0[j*8 + gid]),
                     __float_as_uint(Vr1[j*8 + gid]));
        }

        __syncthreads();                 // all warps done with stage s tiles
        if (kt + 2 < nkv) load_kv(kt + 2, s);
    }

    // ---- normalize + write Y (tf32-rounded) ----
    const float i0 = 1.f / l0, i1 = 1.f / l1;
    float* y0 = &Y[(u64)(rowQ0 + w*16 + gid)*DM + h*HD + tig*2];
    float* y1 = y0 + 8*DM;
    #pragma unroll
    for (int j = 0; j < 8; ++j) {
        *(float2*)&y0[j*8] = make_float2(rtf32(od[j][0]*i0), rtf32(od[j][1]*i0));
        *(float2*)&y1[j*8] = make_float2(rtf32(od[j][2]*i1), rtf32(od[j][3]*i1));
    }
}

// ---------------- launch ----------------
extern "C" void kernel_launch(void* const* d_in, const int* in_sizes, int n_in,
                              void* d_out, int out_size) {
    const float* x  = (const float*)d_in[0];
    const float* Wq = (const float*)d_in[1];
    const float* Wk = (const float*)d_in[2];
    const float* Wv = (const float*)d_in[3];
    const float* Wo = (const float*)d_in[4];
    float* out = (float*)d_out;

    float *Qb, *Ktb, *Vb, *Yb, *xr, *Wqr, *Wor;
    cudaGetSymbolAddress((void**)&Qb,  g_Q);
    cudaGetSymbolAddress((void**)&Ktb, g_Kt);
    cudaGetSymbolAddress((void**)&Vb,  g_V);
    cudaGetSymbolAddress((void**)&Yb,  g_Y);
    cudaGetSymbolAddress((void**)&xr,  g_xr);
    cudaGetSymbolAddress((void**)&Wqr, g_Wqr);
    cudaGetSymbolAddress((void**)&Wor, g_Wor);

    const int fsm = (4*TILEF + 8*16*68) * (int)sizeof(float);  // 108544 B
    cudaFuncSetAttribute(flash5, cudaFuncAttributeMaxDynamicSharedMemorySize, fsm);
    const int gsm = 2 * WSTAGE * (int)sizeof(float);           // 70656 B
    cudaFuncSetAttribute(wgemm, cudaFuncAttributeMaxDynamicSharedMemorySize, gsm);

    // tf32 pre-round
    roundtf<<<(BT*DM/4 + 255)/256, 256>>>(x,  xr,  BT*DM/4);
    roundtf<<<(DM*DM/4 + 255)/256, 256>>>(Wq, Wqr, DM*DM/4);
    roundtf<<<(DM*DM/4 + 255)/256, 256>>>(Wo, Wor, DM*DM/4);

    // Q = x @ Wq  (wmma tf32)
    wgemm<<<dim3(DM/128, BT/128), 128, gsm>>>(xr, Wqr, Qb, BT, DM, DM);
    // K^T = (x @ Wk)^T -> [64][4096], tf32-rounded
    sgemm2<64,64,16,4,4,true ,true><<<dim3(1, BT/64), 256>>>(x, Wk, Ktb, BT, HD, DM);
    // V = x @ Wv, tf32-rounded
    sgemm2<64,64,16,4,4,false,true><<<dim3(1, BT/64), 256>>>(x, Wv, Vb, BT, HD, DM);
    // causal MQA attention -> Y (PTX mma tf32)
    flash5<<<dim3(TS/128, NH, 2), 256, fsm>>>(Qb, Ktb, Vb, Yb);
    // out = Y @ Wo  (wmma tf32)
    wgemm<<<dim3(DM/128, BT/128), 128, gsm>>>(Yb, Wor, out, BT, DM, DM);
}

// round 13
// speedup vs baseline: 2.7675x; 1.2566x over previous
#include <cuda_runtime.h>
#include <cstdint>

typedef unsigned long long u64;

#define BT 4096      // B*T
#define DM 1024
#define NH 16
#define HD 64
#define TS 2048

// ---------------- scratch ----------------
__device__ float g_Q  [BT*DM];   // 16 MB (natural [bt][d])
__device__ float g_Kt [HD*BT];   // 1 MB  (TRANSPOSED [kk][bt], tf32-rounded)
__device__ float g_V  [BT*HD];   // 1 MB  (natural [bt][kk], tf32-rounded)
__device__ float g_Y  [BT*DM];   // 16 MB (tf32-rounded by flash epilogue)
__device__ float g_xr [BT*DM];   // 16 MB (x, tf32-rounded)
__device__ float g_Wqr[DM*DM];   // 4 MB
__device__ float g_Wor[DM*DM];   // 4 MB

// ---------------- helpers ----------------
__device__ __forceinline__ void fma2(u64& d, u64 a, u64 b){
    asm("fma.rn.f32x2 %0, %1, %2, %0;" : "+l"(d) : "l"(a), "l"(b));
}
__device__ __forceinline__ u64 dup2(float x){
    u64 r; asm("mov.b64 %0, {%1, %1};" : "=l"(r) : "f"(x)); return r;
}
__device__ __forceinline__ float2 unpk(u64 v){
    float2 f; asm("mov.b64 {%0, %1}, %2;" : "=f"(f.x), "=f"(f.y) : "l"(v)); return f;
}
__device__ __forceinline__ float rtf32(float x){
    float r; asm("cvt.rna.tf32.f32 %0, %1;" : "=f"(r) : "f"(x)); return r;
}
__device__ __forceinline__ void cpasync16(uint32_t dst, const float* src){
    asm volatile("cp.async.cg.shared.global [%0], [%1], 16;" :: "r"(dst), "l"(src) : "memory");
}
__device__ __forceinline__ uint32_t smem_u32(const void* p){
    uint32_t a; asm("{ .reg .u64 t; cvta.to.shared.u64 t, %1; cvt.u32.u64 %0, t; }"
                    : "=r"(a) : "l"(p)); return a;
}
// m16n8k8 tf32 mma, D += A*B (D aliases C)
__device__ __forceinline__ void mma8(float* d, const uint32_t* a, uint32_t b0, uint32_t b1){
    asm volatile("mma.sync.aligned.m16n8k8.row.col.f32.tf32.tf32.f32 "
        "{%0,%1,%2,%3}, {%4,%5,%6,%7}, {%8,%9}, {%0,%1,%2,%3};"
        : "+f"(d[0]), "+f"(d[1]), "+f"(d[2]), "+f"(d[3])
        : "r"(a[0]), "r"(a[1]), "r"(a[2]), "r"(a[3]), "r"(b0), "r"(b1));
}

// ---------------- tf32 pre-round ----------------
__global__ __launch_bounds__(256)
void roundtf(const float* __restrict__ src, float* __restrict__ dst, int n4){
    int i = blockIdx.x * blockDim.x + threadIdx.x;
    if (i >= n4) return;
    float4 v = ((const float4*)src)[i];
    v.x = rtf32(v.x); v.y = rtf32(v.y); v.z = rtf32(v.z); v.w = rtf32(v.w);
    ((float4*)dst)[i] = v;
}

// ---------------- wgemm2: PTX-mma tf32 GEMM -------------------------------
// C[M,N] = A[M,K] @ B[K,N], inputs tf32-pre-rounded. Block 128x128, BK=32,
// 8 warps (2m x 4n), warp tile 64x32 = 4x4 m16n8k8 frags (64 acc regs).
// 3-stage cp.async pipeline; conflict-free scalar-LDS fragment loads.
#define G2LDA 36
#define G2LDB 136
#define G2STG (128*G2LDA + 32*G2LDB)   // 8960 floats / stage

__global__ __launch_bounds__(256, 2)
void wgemm2(const float* __restrict__ A, const float* __restrict__ B,
            float* __restrict__ C, int M, int N, int K)
{
    extern __shared__ float ws[];
    const uint32_t sbase = smem_u32(ws);

    const int tid  = threadIdx.x;
    const int w    = tid >> 5;
    const int lane = tid & 31;
    const int gid  = lane >> 2;     // 0..7
    const int tig  = lane & 3;      // 0..3
    const int wm   = w & 1;         // 64-row strip
    const int wn   = w >> 1;        // 32-col strip
    const int rowBase = blockIdx.y * 128;
    const int colBase = blockIdx.x * 128;

    auto load_stage = [&](int it, int s){
        const int bk = it * 32;
        const uint32_t sa = sbase + (uint32_t)s * (G2STG*4u);
        #pragma unroll
        for (int i = 0; i < 4; ++i) {            // A: 128 x 32
            int c = tid + 256*i;
            int row = c >> 3, seg = c & 7;
            cpasync16(sa + (uint32_t)(row*G2LDA + seg*4)*4u,
                      &A[(u64)(rowBase+row)*K + bk + seg*4]);
        }
        const uint32_t sb = sa + 128u*G2LDA*4u;
        #pragma unroll
        for (int i = 0; i < 4; ++i) {            // B: 32 x 128
            int c = tid + 256*i;
            int row = c >> 5, seg = c & 31;
            cpasync16(sb + (uint32_t)(row*G2LDB + seg*4)*4u,
                      &B[(u64)(bk+row)*N + colBase + seg*4]);
        }
        asm volatile("cp.async.commit_group;" ::: "memory");
    };

    float acc[4][4][4];
    #pragma unroll
    for (int i = 0; i < 4; ++i)
        #pragma unroll
        for (int j = 0; j < 4; ++j)
            #pragma unroll
            for (int k = 0; k < 4; ++k) acc[i][j][k] = 0.f;

    const int nIt = K / 32;
    load_stage(0, 0);
    load_stage(1, 1);
    load_stage(2, 2);

    int s = 0;
    for (int it = 0; it < nIt; ++it) {
        if (it + 3 < nIt) asm volatile("cp.async.wait_group 2;" ::: "memory");
        else              asm volatile("cp.async.wait_group 0;" ::: "memory");
        __syncthreads();
        const float* As_ = ws + s*G2STG;
        const float* Bs_ = As_ + 128*G2LDA;

        #pragma unroll
        for (int ks = 0; ks < 32; ks += 8) {
            uint32_t af[4][4];
            uint32_t bf[4][2];
            #pragma unroll
            for (int i = 0; i < 4; ++i) {
                const float* ap = As_ + (wm*64 + i*16 + gid)*G2LDA + ks + tig;
                af[i][0] = __float_as_uint(ap[0]);
                af[i][1] = __float_as_uint(ap[8*G2LDA]);
                af[i][2] = __float_as_uint(ap[4]);
                af[i][3] = __float_as_uint(ap[8*G2LDA + 4]);
            }
            #pragma unroll
            for (int j = 0; j < 4; ++j) {
                const int col = wn*32 + j*8 + gid;
                bf[j][0] = __float_as_uint(Bs_[(ks+tig  )*G2LDB + col]);
                bf[j][1] = __float_as_uint(Bs_[(ks+tig+4)*G2LDB + col]);
            }
            #pragma unroll
            for (int i = 0; i < 4; ++i)
                #pragma unroll
                for (int j = 0; j < 4; ++j)
                    mma8(acc[i][j], af[i], bf[j][0], bf[j][1]);
        }
        __syncthreads();
        if (it + 3 < nIt) load_stage(it + 3, s);
        s = (s == 2) ? 0 : s + 1;
    }

    // epilogue: C-layout frags -> global (float2 per row-half)
    #pragma unroll
    for (int i = 0; i < 4; ++i) {
        const int row0 = rowBase + wm*64 + i*16 + gid;
        #pragma unroll
        for (int j = 0; j < 4; ++j) {
            const int col = colBase + wn*32 + j*8 + tig*2;
            *(float2*)&C[(u64)row0*N + col]     = make_float2(acc[i][j][0], acc[i][j][1]);
            *(float2*)&C[(u64)(row0+8)*N + col] = make_float2(acc[i][j][2], acc[i][j][3]);
        }
    }
}

// ---------------- scalar packed GEMM for small K/V projections --------------
template<int BM, int BN, int BK, int TM, int TN, bool TRANS, bool R>
__global__ __launch_bounds__(256)
void sgemm2(const float* __restrict__ A, const float* __restrict__ Bm,
            float* __restrict__ C, int M, int N, int K)
{
    __shared__ float As[BK*BM];
    __shared__ float Bs[BK*BN];

    const int tid = threadIdx.x;
    const int tc  = tid % (BN/TN);
    const int tr  = tid / (BN/TN);
    const int rowBase = blockIdx.y * BM;
    const int colBase = blockIdx.x * BN;

    const int irA = tid / (BK/4);
    const int icA = (tid % (BK/4)) * 4;
    constexpr int sA = (256*4)/BK;
    const int irB = tid / (BN/4);
    const int icB = (tid % (BN/4)) * 4;
    constexpr int sB = (256*4)/BN;

    u64 res2[TM*(TN/2)];
    #pragma unroll
    for (int i = 0; i < TM*(TN/2); ++i) res2[i] = 0ull;

    for (int bk = 0; bk < K; bk += BK) {
        #pragma unroll
        for (int off = 0; off < BM; off += sA) {
            float4 t = *(const float4*)&A[(rowBase+irA+off)*K + bk + icA];
            As[(icA+0)*BM + irA+off] = t.x;
            As[(icA+1)*BM + irA+off] = t.y;
            As[(icA+2)*BM + irA+off] = t.z;
            As[(icA+3)*BM + irA+off] = t.w;
        }
        #pragma unroll
        for (int off = 0; off < BK; off += sB)
            *(float4*)&Bs[(irB+off)*BN + icB] =
                *(const float4*)&Bm[(bk+irB+off)*N + colBase + icB];
        __syncthreads();

        #pragma unroll
        for (int kk = 0; kk < BK; ++kk) {
            float regM[TM]; u64 regN[TN/2];
            #pragma unroll
            for (int q = 0; q < TM/4; ++q)
                *(float4*)&regM[q*4] = *(const float4*)&As[kk*BM + tr*TM + q*4];
            #pragma unroll
            for (int q = 0; q < TN/4; ++q) {
                ulonglong2 t = *(const ulonglong2*)&Bs[kk*BN + tc*TN + q*4];
                regN[q*2] = t.x; regN[q*2+1] = t.y;
            }
            #pragma unroll
            for (int i = 0; i < TM; ++i) {
                u64 a = dup2(regM[i]);
                #pragma unroll
                for (int j = 0; j < TN/2; ++j) fma2(res2[i*(TN/2)+j], a, regN[j]);
            }
        }
        __syncthreads();
    }

    if (!TRANS) {
        #pragma unroll
        for (int i = 0; i < TM; ++i)
            #pragma unroll
            for (int jq = 0; jq < TN/4; ++jq) {
                float2 a = unpk(res2[i*(TN/2)+jq*2]);
                float2 b = unpk(res2[i*(TN/2)+jq*2+1]);
                float4 o = make_float4(a.x, a.y, b.x, b.y);
                if (R) { o.x=rtf32(o.x); o.y=rtf32(o.y); o.z=rtf32(o.z); o.w=rtf32(o.w); }
                *(float4*)&C[(rowBase+tr*TM+i)*N + colBase+tc*TN+jq*4] = o;
            }
    } else {
        float rs[TM*TN];
        #pragma unroll
        for (int i = 0; i < TM; ++i)
            #pragma unroll
            for (int j = 0; j < TN/2; ++j) {
                float2 a = unpk(res2[i*(TN/2)+j]);
                rs[i*TN + j*2] = a.x; rs[i*TN + j*2+1] = a.y;
            }
        #pragma unroll
        for (int j = 0; j < TN; ++j)
            #pragma unroll
            for (int iq = 0; iq < TM/4; ++iq) {
                float4 o = make_float4(rs[(iq*4+0)*TN+j], rs[(iq*4+1)*TN+j],
                                       rs[(iq*4+2)*TN+j], rs[(iq*4+3)*TN+j]);
                if (R) { o.x=rtf32(o.x); o.y=rtf32(o.y); o.z=rtf32(o.z); o.w=rtf32(o.w); }
                *(float4*)&C[(colBase+tc*TN+j)*M + rowBase+tr*TM+iq*4] = o;
            }
    }
}

// ---------------- flash5: register-resident PTX-mma flash attention ---------
#define TILEF (64*72)     // floats per K or V tile (ld=72)
__global__ __launch_bounds__(256)
void flash5(const float* __restrict__ Q, const float* __restrict__ Kt,
            const float* __restrict__ V, float* __restrict__ Y)
{
    extern __shared__ float smx[];
    const uint32_t sbase = smem_u32(smx);

    const int qt = (int)(gridDim.x - 1) - (int)blockIdx.x;   // heavy first
    const int h  = blockIdx.y, b = blockIdx.z;
    const int tid = threadIdx.x;
    const int w   = tid >> 5;
    const int lane = tid & 31;
    const int gid = lane >> 2;
    const int tig = lane & 3;
    const int rowQ0 = b*TS + qt*128;
    const int rowK0 = b*TS;
    const int qr0 = qt*128 + w*16 + gid;
    const int nkv = 2*qt + 2;

    float* Pw = smx + 4*TILEF + w*(16*68);

    auto load_kv = [&](int kt, int s){
        const int colK0 = kt*64;
        const uint32_t ka = sbase + (uint32_t)s*(2*TILEF*4u);
        const uint32_t va = ka + TILEF*4u;
        #pragma unroll
        for (int i = 0; i < 4; ++i) {
            int c = tid + 256*i;
            int row = c >> 4, seg = c & 15;
            cpasync16(ka + (uint32_t)(row*72 + seg*4)*4u,
                      &Kt[(u64)row*BT + rowK0 + colK0 + seg*4]);
            cpasync16(va + (uint32_t)(row*72 + seg*4)*4u,
                      &V[(u64)(rowK0 + colK0 + row)*HD + seg*4]);
        }
        asm volatile("cp.async.commit_group;" ::: "memory");
    };

    load_kv(0, 0);
    if (nkv > 1) load_kv(1, 1);

    uint32_t qa[8][4];
    {
        const float* qp = &Q[(u64)(rowQ0 + w*16 + gid)*DM + h*HD + tig];
        const float* qp8 = qp + 8*DM;
        #pragma unroll
        for (int kf = 0; kf < 8; ++kf) {
            qa[kf][0] = __float_as_uint(rtf32(0.125f * qp [kf*8]));
            qa[kf][1] = __float_as_uint(rtf32(0.125f * qp8[kf*8]));
            qa[kf][2] = __float_as_uint(rtf32(0.125f * qp [kf*8 + 4]));
            qa[kf][3] = __float_as_uint(rtf32(0.125f * qp8[kf*8 + 4]));
        }
    }

    float od[8][4];
    #pragma unroll
    for (int j = 0; j < 8; ++j)
        #pragma unroll
        for (int k = 0; k < 4; ++k) od[j][k] = 0.f;
    float m0 = -1e30f, m1 = -1e30f, l0 = 0.f, l1 = 0.f;

    for (int kt = 0; kt < nkv; ++kt) {
        const int s = kt & 1;
        if (kt + 1 < nkv) asm volatile("cp.async.wait_group 1;" ::: "memory");
        else              asm volatile("cp.async.wait_group 0;" ::: "memory");
        __syncthreads();
        const float* Ks = smx + s*(2*TILEF);
        const float* Vs = Ks + TILEF;

        float sd[8][4];
        #pragma unroll
        for (int j = 0; j < 8; ++j)
            #pragma unroll
            for (int k = 0; k < 4; ++k) sd[j][k] = 0.f;
        #pragma unroll
        for (int kf = 0; kf < 8; ++kf) {
            const float* Kr0 = Ks + (kf*8 + tig)*72;
            const float* Kr1 = Kr0 + 4*72;
            #pragma unroll
            for (int j = 0; j < 8; ++j)
                mma8(sd[j], qa[kf],
                     __float_as_uint(Kr0[j*8 + gid]),
                     __float_as_uint(Kr1[j*8 + gid]));
        }

        const int colB = kt*64 + tig*2;
        if (kt*64 + 63 > qr0) {
            #pragma unroll
            for (int j = 0; j < 8; ++j) {
                int c0 = colB + j*8;
                if (c0     > qr0)   sd[j][0] = -1e30f;
                if (c0 + 1 > qr0)   sd[j][1] = -1e30f;
                if (c0     > qr0+8) sd[j][2] = -1e30f;
                if (c0 + 1 > qr0+8) sd[j][3] = -1e30f;
            }
        }

        float mx0 = sd[0][0], mx1 = sd[0][2];
        #pragma unroll
        for (int j = 0; j < 8; ++j) {
            mx0 = fmaxf(mx0, fmaxf(sd[j][0], sd[j][1]));
            mx1 = fmaxf(mx1, fmaxf(sd[j][2], sd[j][3]));
        }
        mx0 = fmaxf(mx0, __shfl_xor_sync(0xffffffffu, mx0, 1));
        mx0 = fmaxf(mx0, __shfl_xor_sync(0xffffffffu, mx0, 2));
        mx1 = fmaxf(mx1, __shfl_xor_sync(0xffffffffu, mx1, 1));
        mx1 = fmaxf(mx1, __shfl_xor_sync(0xffffffffu, mx1, 2));
        float mn0 = fmaxf(m0, mx0), mn1 = fmaxf(m1, mx1);
        float sc0 = __expf(m0 - mn0), sc1 = __expf(m1 - mn1);
        float ps0 = 0.f, ps1 = 0.f;
        #pragma unroll
        for (int j = 0; j < 8; ++j) {
            sd[j][0] = __expf(sd[j][0] - mn0); ps0 += sd[j][0];
            sd[j][1] = __expf(sd[j][1] - mn0); ps0 += sd[j][1];
            sd[j][2] = __expf(sd[j][2] - mn1); ps1 += sd[j][2];
            sd[j][3] = __expf(sd[j][3] - mn1); ps1 += sd[j][3];
        }
        ps0 += __shfl_xor_sync(0xffffffffu, ps0, 1);
        ps0 += __shfl_xor_sync(0xffffffffu, ps0, 2);
        ps1 += __shfl_xor_sync(0xffffffffu, ps1, 1);
        ps1 += __shfl_xor_sync(0xffffffffu, ps1, 2);
        l0 = l0*sc0 + ps0; l1 = l1*sc1 + ps1;
        m0 = mn0; m1 = mn1;
        #pragma unroll
        for (int j = 0; j < 8; ++j) {
            od[j][0] *= sc0; od[j][1] *= sc0;
            od[j][2] *= sc1; od[j][3] *= sc1;
        }

        __syncwarp();
        #pragma unroll
        for (int j = 0; j < 8; ++j) {
            *(float2*)&Pw[ gid   *68 + j*8 + tig*2] =
                make_float2(rtf32(sd[j][0]), rtf32(sd[j][1]));
            *(float2*)&Pw[(gid+8)*68 + j*8 + tig*2] =
                make_float2(rtf32(sd[j][2]), rtf32(sd[j][3]));
        }
        __syncwarp();

        #pragma unroll
        for (int kf = 0; kf < 8; ++kf) {
            uint32_t pa[4];
            pa[0] = __float_as_uint(Pw[ gid   *68 + kf*8 + tig]);
            pa[1] = __float_as_uint(Pw[(gid+8)*68 + kf*8 + tig]);
            pa[2] = __float_as_uint(Pw[ gid   *68 + kf*8 + tig + 4]);
            pa[3] = __float_as_uint(Pw[(gid+8)*68 + kf*8 + tig + 4]);
            const float* Vr0 = Vs + (kf*8 + tig)*72;
            const float* Vr1 = Vr0 + 4*72;
            #pragma unroll
            for (int j = 0; j < 8; ++j)
                mma8(od[j], pa,
                     __float_as_uint(Vr0[j*8 + gid]),
                     __float_as_uint(Vr1[j*8 + gid]));
        }

        __syncthreads();
        if (kt + 2 < nkv) load_kv(kt + 2, s);
    }

    const float i0 = 1.f / l0, i1 = 1.f / l1;
    float* y0 = &Y[(u64)(rowQ0 + w*16 + gid)*DM + h*HD + tig*2];
    float* y1 = y0 + 8*DM;
    #pragma unroll
    for (int j = 0; j < 8; ++j) {
        *(float2*)&y0[j*8] = make_float2(rtf32(od[j][0]*i0), rtf32(od[j][1]*i0));
        *(float2*)&y1[j*8] = make_float2(rtf32(od[j][2]*i1), rtf32(od[j][3]*i1));
    }
}

// ---------------- launch ----------------
extern "C" void kernel_launch(void* const* d_in, const int* in_sizes, int n_in,
                              void* d_out, int out_size) {
    const float* x  = (const float*)d_in[0];
    const float* Wq = (const float*)d_in[1];
    const float* Wk = (const float*)d_in[2];
    const float* Wv = (const float*)d_in[3];
    const float* Wo = (const float*)d_in[4];
    float* out = (float*)d_out;

    float *Qb, *Ktb, *Vb, *Yb, *xr, *Wqr, *Wor;
    cudaGetSymbolAddress((void**)&Qb,  g_Q);
    cudaGetSymbolAddress((void**)&Ktb, g_Kt);
    cudaGetSymbolAddress((void**)&Vb,  g_V);
    cudaGetSymbolAddress((void**)&Yb,  g_Y);
    cudaGetSymbolAddress((void**)&xr,  g_xr);
    cudaGetSymbolAddress((void**)&Wqr, g_Wqr);
    cudaGetSymbolAddress((void**)&Wor, g_Wor);

    const int fsm = (4*TILEF + 8*16*68) * (int)sizeof(float);  // 108544 B
    cudaFuncSetAttribute(flash5, cudaFuncAttributeMaxDynamicSharedMemorySize, fsm);
    const int gsm = 3 * G2STG * (int)sizeof(float);            // 107520 B
    cudaFuncSetAttribute(wgemm2, cudaFuncAttributeMaxDynamicSharedMemorySize, gsm);

    // tf32 pre-round
    roundtf<<<(BT*DM/4 + 255)/256, 256>>>(x,  xr,  BT*DM/4);
    roundtf<<<(DM*DM/4 + 255)/256, 256>>>(Wq, Wqr, DM*DM/4);
    roundtf<<<(DM*DM/4 + 255)/256, 256>>>(Wo, Wor, DM*DM/4);

    // Q = x @ Wq  (PTX mma tf32)
    wgemm2<<<dim3(DM/128, BT/128), 256, gsm>>>(xr, Wqr, Qb, BT, DM, DM);
    // K^T = (x @ Wk)^T -> [64][4096], tf32-rounded
    sgemm2<64,64,16,4,4,true ,true><<<dim3(1, BT/64), 256>>>(x, Wk, Ktb, BT, HD, DM);
    // V = x @ Wv, tf32-rounded
    sgemm2<64,64,16,4,4,false,true><<<dim3(1, BT/64), 256>>>(x, Wv, Vb, BT, HD, DM);
    // causal MQA attention -> Y (PTX mma tf32)
    flash5<<<dim3(TS/128, NH, 2), 256, fsm>>>(Qb, Ktb, Vb, Yb);
    // out = Y @ Wo  (PTX mma tf32)
    wgemm2<<<dim3(DM/128, BT/128), 256, gsm>>>(Yb, Wor, out, BT, DM, DM);
}